// round 2
// baseline (speedup 1.0000x reference)
#include <cuda_runtime.h>
#include <cuda_bf16.h>
#include <cstdint>

// ---------------- problem constants ----------------
#define BB 8
#define TT 1024
#define DD 1024
#define FF 4096
#define MM (BB * TT)          // 8192 rows
#define EPS_LN 1e-3f

// ---------------- scratch (static device globals; no allocation) ----------------
__device__ float g_xn  [(size_t)MM * DD];   // ln1(x)
__device__ float g_xk  [(size_t)MM * DD];   // mixed k-input, later reused for r*wkv
__device__ float g_xv  [(size_t)MM * DD];   // mixed v-input, later reused for xk2
__device__ float g_xr  [(size_t)MM * DD];   // mixed r-input, later reused for xr2
__device__ float g_k   [(size_t)MM * DD];
__device__ float g_v   [(size_t)MM * DD];
__device__ float g_r   [(size_t)MM * DD];
__device__ float g_wkv [(size_t)MM * DD];
__device__ float g_x1  [(size_t)MM * DD];
__device__ float g_xn2 [(size_t)MM * DD];
__device__ float g_rc  [(size_t)MM * DD];
__device__ float g_kc  [(size_t)MM * FF];   // 134 MB

// ---------------- LayerNorm: one block per row ----------------
__global__ __launch_bounds__(256)
void ln_kernel(const float* __restrict__ x, const float* __restrict__ gamma,
               const float* __restrict__ beta, float* __restrict__ y,
               float* __restrict__ last_out) {
    __shared__ float red0[8], red1[8];
    int row = blockIdx.x;
    const float* xr = x + (size_t)row * DD;
    float s = 0.f, s2 = 0.f;
    #pragma unroll
    for (int i = threadIdx.x; i < DD; i += 256) {
        float v = xr[i];
        s += v; s2 += v * v;
    }
    #pragma unroll
    for (int o = 16; o; o >>= 1) {
        s  += __shfl_down_sync(0xffffffffu, s,  o);
        s2 += __shfl_down_sync(0xffffffffu, s2, o);
    }
    int lane = threadIdx.x & 31, wid = threadIdx.x >> 5;
    if (lane == 0) { red0[wid] = s; red1[wid] = s2; }
    __syncthreads();
    s = 0.f; s2 = 0.f;
    #pragma unroll
    for (int i = 0; i < 8; i++) { s += red0[i]; s2 += red1[i]; }
    const float invD = 1.0f / DD;
    float mu  = s * invD;
    float var = s2 * invD - mu * mu;
    float inv = rsqrtf(var + EPS_LN);

    float* yr = y + (size_t)row * DD;
    bool is_last = ((row % TT) == (TT - 1));
    float* lr = last_out + (size_t)(row / TT) * DD;
    #pragma unroll
    for (int i = threadIdx.x; i < DD; i += 256) {
        float v = (xr[i] - mu) * inv * gamma[i] + beta[i];
        yr[i] = v;
        if (is_last) lr[i] = v;
    }
}

// ---------------- token-shift mix (2 or 3 outputs) ----------------
__global__ __launch_bounds__(256)
void mix_kernel(const float* __restrict__ xn, const float* __restrict__ init,
                const float* __restrict__ mk, const float* __restrict__ mv,
                const float* __restrict__ mr,
                float* __restrict__ ok, float* __restrict__ ov,
                float* __restrict__ orr) {
    size_t idx = (size_t)blockIdx.x * 256 + threadIdx.x;
    int d = (int)(idx & (DD - 1));
    size_t row = idx >> 10;            // idx / DD
    int t = (int)(row & (TT - 1));
    int b = (int)(row >> 10);          // row / TT
    float cur  = xn[idx];
    float prev = t ? xn[idx - DD] : init[(size_t)b * DD + d];
    float m;
    m = mk[d]; ok[idx]  = m * cur + (1.f - m) * prev;
    if (ov) { m = mv[d]; ov[idx] = m * cur + (1.f - m) * prev; }
    m = mr[d]; orr[idx] = m * cur + (1.f - m) * prev;
}

// ---------------- elementwise multiply ----------------
__global__ __launch_bounds__(256)
void mul_kernel(const float* __restrict__ a, const float* __restrict__ b,
                float* __restrict__ c) {
    size_t idx = (size_t)blockIdx.x * 256 + threadIdx.x;
    c[idx] = a[idx] * b[idx];
}

// ---------------- WKV scan: one thread per (b, d) channel ----------------
__global__ __launch_bounds__(256)
void wkv_scan(const float* __restrict__ kbuf, const float* __restrict__ vbuf,
              const float* __restrict__ a0, const float* __restrict__ b0,
              const float* __restrict__ p0,
              const float* __restrict__ decay, const float* __restrict__ first,
              float* __restrict__ wkvbuf,
              float* __restrict__ aa_out, float* __restrict__ bb_out,
              float* __restrict__ pp_out) {
    int idx = blockIdx.x * 256 + threadIdx.x;   // 0 .. B*D-1
    int d = idx & (DD - 1);
    int b = idx >> 10;
    float w = -__expf(decay[d]);
    float u = first[d];
    float aa = a0[idx], bb = b0[idx], pp = p0[idx];
    const float* kp = kbuf + (size_t)b * TT * DD + d;
    const float* vp = vbuf + (size_t)b * TT * DD + d;
    float* op = wkvbuf + (size_t)b * TT * DD + d;
    for (int t = 0; t < TT; t++) {
        float kt = kp[(size_t)t * DD];
        float vt = vp[(size_t)t * DD];
        float ww = u + kt;
        float p  = fmaxf(pp, ww);
        float e1 = __expf(pp - p);
        float e2 = __expf(ww - p);
        op[(size_t)t * DD] = (e1 * aa + e2 * vt) / (e1 * bb + e2);
        float ww2 = pp + w;
        float p2  = fmaxf(ww2, kt);
        float e1b = __expf(ww2 - p2);
        float e2b = __expf(kt - p2);
        aa = e1b * aa + e2b * vt;
        bb = e1b * bb + e2b;
        pp = p2;
    }
    aa_out[idx] = aa; bb_out[idx] = bb; pp_out[idx] = pp;
}

// ---------------- fp32 tiled SGEMM with fused epilogue ----------------
// C[M,N] = epi(A[M,K] @ W[K,N]);  epi: act(0 none,1 sigmoid,2 relu^2),
// then optional elementwise *mul and +add (same [M,N] layout).
#define BM 128
#define BN 128
#define BKK 8
__global__ __launch_bounds__(256)
void sgemm(const float* __restrict__ A, const float* __restrict__ W,
           float* __restrict__ C, int Mn, int Nn, int Kn,
           int act, const float* __restrict__ mul, const float* __restrict__ add) {
    __shared__ __align__(16) float As[BKK][BM];
    __shared__ __align__(16) float Bs[BKK][BN];
    int tid = threadIdx.x;
    int tr = tid >> 4;          // 0..15
    int tc = tid & 15;          // 0..15
    float acc[8][8];
    #pragma unroll
    for (int i = 0; i < 8; i++)
        #pragma unroll
        for (int j = 0; j < 8; j++) acc[i][j] = 0.f;

    int aRow = tid >> 1;             // 0..127
    int aCol = (tid & 1) << 2;       // 0 or 4
    int bRow = tid >> 5;             // 0..7
    int bCol = (tid & 31) << 2;      // 0..124

    const float* Aptr = A + (size_t)(blockIdx.y * BM) * Kn;
    const float* Wptr = W + (size_t)blockIdx.x * BN;

    for (int k0 = 0; k0 < Kn; k0 += BKK) {
        float4 a = *(const float4*)(Aptr + (size_t)aRow * Kn + k0 + aCol);
        As[aCol + 0][aRow] = a.x;
        As[aCol + 1][aRow] = a.y;
        As[aCol + 2][aRow] = a.z;
        As[aCol + 3][aRow] = a.w;
        float4 bv = *(const float4*)(Wptr + (size_t)(k0 + bRow) * Nn + bCol);
        *(float4*)&Bs[bRow][bCol] = bv;
        __syncthreads();
        #pragma unroll
        for (int kk = 0; kk < BKK; kk++) {
            float4 ra0 = *(const float4*)&As[kk][tr * 8];
            float4 ra1 = *(const float4*)&As[kk][tr * 8 + 4];
            float4 rb0 = *(const float4*)&Bs[kk][tc * 8];
            float4 rb1 = *(const float4*)&Bs[kk][tc * 8 + 4];
            float ra[8] = {ra0.x, ra0.y, ra0.z, ra0.w, ra1.x, ra1.y, ra1.z, ra1.w};
            float rb[8] = {rb0.x, rb0.y, rb0.z, rb0.w, rb1.x, rb1.y, rb1.z, rb1.w};
            #pragma unroll
            for (int i = 0; i < 8; i++)
                #pragma unroll
                for (int j = 0; j < 8; j++)
                    acc[i][j] += ra[i] * rb[j];
        }
        __syncthreads();
    }

    int crow0 = blockIdx.y * BM + tr * 8;
    int ccol0 = blockIdx.x * BN + tc * 8;
    #pragma unroll
    for (int i = 0; i < 8; i++) {
        size_t base = (size_t)(crow0 + i) * Nn + ccol0;
        #pragma unroll
        for (int j = 0; j < 8; j++) {
            float v = acc[i][j];
            if (act == 1)      v = 1.f / (1.f + __expf(-v));
            else if (act == 2) { v = fmaxf(v, 0.f); v = v * v; }
            if (mul) v *= mul[base + j];
            if (add) v += add[base + j];
            C[base + j] = v;
        }
    }
}

// ---------------- host driver ----------------
extern "C" void kernel_launch(void* const* d_in, const int* in_sizes, int n_in,
                              void* d_out, int out_size) {
    const float* x        = (const float*)d_in[0];
    const float* att_x    = (const float*)d_in[1];
    const float* att_a    = (const float*)d_in[2];
    const float* att_b    = (const float*)d_in[3];
    const float* att_p    = (const float*)d_in[4];
    const float* ffn_x    = (const float*)d_in[5];
    const float* ln1_g    = (const float*)d_in[6];
    const float* ln1_b    = (const float*)d_in[7];
    const float* ln2_g    = (const float*)d_in[8];
    const float* ln2_b    = (const float*)d_in[9];
    const float* tm_mix_k = (const float*)d_in[10];
    const float* tm_mix_v = (const float*)d_in[11];
    const float* tm_mix_r = (const float*)d_in[12];
    const float* tm_decay = (const float*)d_in[13];
    const float* tm_first = (const float*)d_in[14];
    const float* Wk       = (const float*)d_in[15];
    const float* Wv       = (const float*)d_in[16];
    const float* Wr       = (const float*)d_in[17];
    const float* Wo       = (const float*)d_in[18];
    const float* cm_mix_k = (const float*)d_in[19];
    const float* cm_mix_r = (const float*)d_in[20];
    const float* Ck       = (const float*)d_in[21];
    const float* Cr       = (const float*)d_in[22];
    const float* Cv       = (const float*)d_in[23];

    float* out      = (float*)d_out;                       // [B,T,D]
    float* xn_last  = out + (size_t)MM * DD;               // [B,D]
    float* aa_out   = xn_last  + (size_t)BB * DD;
    float* bb_out   = aa_out   + (size_t)BB * DD;
    float* pp_out   = bb_out   + (size_t)BB * DD;
    float* xn2_last = pp_out   + (size_t)BB * DD;

    float *xn, *xk, *xv, *xr, *kb, *vb, *rb, *wkv, *x1, *xn2, *rc, *kc;
    cudaGetSymbolAddress((void**)&xn,  g_xn);
    cudaGetSymbolAddress((void**)&xk,  g_xk);
    cudaGetSymbolAddress((void**)&xv,  g_xv);
    cudaGetSymbolAddress((void**)&xr,  g_xr);
    cudaGetSymbolAddress((void**)&kb,  g_k);
    cudaGetSymbolAddress((void**)&vb,  g_v);
    cudaGetSymbolAddress((void**)&rb,  g_r);
    cudaGetSymbolAddress((void**)&wkv, g_wkv);
    cudaGetSymbolAddress((void**)&x1,  g_x1);
    cudaGetSymbolAddress((void**)&xn2, g_xn2);
    cudaGetSymbolAddress((void**)&rc,  g_rc);
    cudaGetSymbolAddress((void**)&kc,  g_kc);

    const int ELT_BLOCKS = (int)(((size_t)MM * DD) / 256);  // 32768

    // ---- time mixing ----
    ln_kernel<<<MM, 256>>>(x, ln1_g, ln1_b, xn, xn_last);
    mix_kernel<<<ELT_BLOCKS, 256>>>(xn, att_x, tm_mix_k, tm_mix_v, tm_mix_r,
                                    xk, xv, xr);
    dim3 gemm_grid_1k(DD / BN, MM / BM);    // (8, 64)
    sgemm<<<gemm_grid_1k, 256>>>(xk, Wk, kb, MM, DD, DD, 0, nullptr, nullptr);
    sgemm<<<gemm_grid_1k, 256>>>(xv, Wv, vb, MM, DD, DD, 0, nullptr, nullptr);
    sgemm<<<gemm_grid_1k, 256>>>(xr, Wr, rb, MM, DD, DD, 1, nullptr, nullptr);

    wkv_scan<<<(BB * DD) / 256, 256>>>(kb, vb, att_a, att_b, att_p,
                                       tm_decay, tm_first, wkv,
                                       aa_out, bb_out, pp_out);

    mul_kernel<<<ELT_BLOCKS, 256>>>(rb, wkv, xk);                 // xk := r * wkv
    sgemm<<<gemm_grid_1k, 256>>>(xk, Wo, x1, MM, DD, DD, 0, nullptr, x); // x1 = x + (r*wkv)@Wo

    // ---- channel mixing ----
    ln_kernel<<<MM, 256>>>(x1, ln2_g, ln2_b, xn2, xn2_last);
    mix_kernel<<<ELT_BLOCKS, 256>>>(xn2, ffn_x, cm_mix_k, nullptr, cm_mix_r,
                                    xv /*xk2*/, nullptr, xr /*xr2*/);

    dim3 gemm_grid_4k(FF / BN, MM / BM);    // (32, 64)
    sgemm<<<gemm_grid_4k, 256>>>(xv, Ck, kc, MM, FF, DD, 2, nullptr, nullptr); // relu()^2
    sgemm<<<gemm_grid_1k, 256>>>(xr, Cr, rc, MM, DD, DD, 1, nullptr, nullptr); // sigmoid
    sgemm<<<gemm_grid_1k, 256>>>(kc, Cv, out, MM, DD, FF, 0, rc, x1);          // out = x1 + rc*(kc@Cv)
}

// round 5
// speedup vs baseline: 2.3572x; 2.3572x over previous
#include <cuda_runtime.h>
#include <cuda_bf16.h>
#include <cstdint>

// ---------------- problem constants ----------------
#define BB 8
#define TT 1024
#define DD 1024
#define FF 4096
#define MM (BB * TT)          // 8192 rows
#define EPS_LN 1e-3f

// ---------------- PTX helpers ----------------
__device__ __forceinline__ uint32_t smem_u32(const void* p) {
    uint32_t a;
    asm("{ .reg .u64 t; cvta.to.shared.u64 t, %1; cvt.u32.u64 %0, t; }"
        : "=r"(a) : "l"(p));
    return a;
}

__device__ __forceinline__ void cpa16(uint32_t dst, const void* src) {
    asm volatile("cp.async.cg.shared.global [%0], [%1], 16;"
                 :: "r"(dst), "l"(src) : "memory");
}
#define CP_COMMIT() asm volatile("cp.async.commit_group;" ::: "memory")
#define CP_WAIT(n)  asm volatile("cp.async.wait_group %0;" :: "n"(n) : "memory")

__device__ __forceinline__ void ldsm4(uint32_t* r, uint32_t a) {
    asm volatile("ldmatrix.sync.aligned.m8n8.x4.shared.b16 {%0,%1,%2,%3}, [%4];"
                 : "=r"(r[0]), "=r"(r[1]), "=r"(r[2]), "=r"(r[3]) : "r"(a));
}

__device__ __forceinline__ void mma_bf16(float* c, const uint32_t* a, const uint32_t* b) {
    asm volatile(
        "mma.sync.aligned.m16n8k16.row.col.f32.bf16.bf16.f32 "
        "{%0,%1,%2,%3}, {%4,%5,%6,%7}, {%8,%9}, {%0,%1,%2,%3};"
        : "+f"(c[0]), "+f"(c[1]), "+f"(c[2]), "+f"(c[3])
        : "r"(a[0]), "r"(a[1]), "r"(a[2]), "r"(a[3]), "r"(b[0]), "r"(b[1]));
}

// ---------------- scratch (static device globals) ----------------
__device__ float g_xn [(size_t)MM * DD];
__device__ float g_kb [(size_t)MM * DD];
__device__ float g_vb [(size_t)MM * DD];
__device__ float g_rb [(size_t)MM * DD];
__device__ float g_wkv[(size_t)MM * DD];
__device__ float g_x1 [(size_t)MM * DD];
__device__ float g_xn2[(size_t)MM * DD];
__device__ float g_rc [(size_t)MM * DD];
// bf16 activation splits
__device__ __nv_bfloat16 g_akh[(size_t)MM * DD];
__device__ __nv_bfloat16 g_akl[(size_t)MM * DD];
__device__ __nv_bfloat16 g_avh[(size_t)MM * DD];
__device__ __nv_bfloat16 g_avl[(size_t)MM * DD];
__device__ __nv_bfloat16 g_arh[(size_t)MM * DD];
__device__ __nv_bfloat16 g_arl[(size_t)MM * DD];
__device__ __nv_bfloat16 g_kch[(size_t)MM * FF];
__device__ __nv_bfloat16 g_kcl[(size_t)MM * FF];
// bf16 transposed weight splits [N, K]
__device__ __nv_bfloat16 g_wkh[(size_t)DD * DD],  g_wkl[(size_t)DD * DD];
__device__ __nv_bfloat16 g_wvh[(size_t)DD * DD],  g_wvl[(size_t)DD * DD];
__device__ __nv_bfloat16 g_wrh[(size_t)DD * DD],  g_wrl[(size_t)DD * DD];
__device__ __nv_bfloat16 g_woh[(size_t)DD * DD],  g_wol[(size_t)DD * DD];
__device__ __nv_bfloat16 g_crh[(size_t)DD * DD],  g_crl[(size_t)DD * DD];
__device__ __nv_bfloat16 g_ckh[(size_t)FF * DD],  g_ckl[(size_t)FF * DD];   // Ck^T
__device__ __nv_bfloat16 g_cvh[(size_t)DD * FF],  g_cvl[(size_t)DD * FF];   // Cv^T

__device__ __forceinline__ void split_store(float v, __nv_bfloat16* hp,
                                            __nv_bfloat16* lp, size_t i) {
    __nv_bfloat16 h = __float2bfloat16(v);
    hp[i] = h;
    lp[i] = __float2bfloat16(v - __bfloat162float(h));
}

// ---------------- LayerNorm ----------------
__global__ __launch_bounds__(256)
void ln_kernel(const float* __restrict__ x, const float* __restrict__ gamma,
               const float* __restrict__ beta, float* __restrict__ y,
               float* __restrict__ last_out) {
    __shared__ float red0[8], red1[8];
    int row = blockIdx.x;
    const float* xr = x + (size_t)row * DD;
    float s = 0.f, s2 = 0.f;
    #pragma unroll
    for (int i = threadIdx.x; i < DD; i += 256) {
        float v = xr[i];
        s += v; s2 += v * v;
    }
    #pragma unroll
    for (int o = 16; o; o >>= 1) {
        s  += __shfl_down_sync(0xffffffffu, s,  o);
        s2 += __shfl_down_sync(0xffffffffu, s2, o);
    }
    int lane = threadIdx.x & 31, wid = threadIdx.x >> 5;
    if (lane == 0) { red0[wid] = s; red1[wid] = s2; }
    __syncthreads();
    s = 0.f; s2 = 0.f;
    #pragma unroll
    for (int i = 0; i < 8; i++) { s += red0[i]; s2 += red1[i]; }
    const float invD = 1.0f / DD;
    float mu  = s * invD;
    float var = s2 * invD - mu * mu;
    float inv = rsqrtf(var + EPS_LN);
    float* yr = y + (size_t)row * DD;
    bool is_last = ((row & (TT - 1)) == (TT - 1));
    float* lr = last_out + (size_t)(row >> 10) * DD;
    #pragma unroll
    for (int i = threadIdx.x; i < DD; i += 256) {
        float v = (xr[i] - mu) * inv * gamma[i] + beta[i];
        yr[i] = v;
        if (is_last) lr[i] = v;
    }
}

// ---------------- token-shift mix -> bf16 hi/lo splits ----------------
__global__ __launch_bounds__(256)
void mix_split(const float* __restrict__ xn, const float* __restrict__ init,
               const float* __restrict__ mk, const float* __restrict__ mv,
               const float* __restrict__ mr,
               __nv_bfloat16* kh, __nv_bfloat16* kl,
               __nv_bfloat16* vh, __nv_bfloat16* vl,
               __nv_bfloat16* rh, __nv_bfloat16* rl) {
    size_t idx = (size_t)blockIdx.x * 256 + threadIdx.x;
    int d = (int)(idx & (DD - 1));
    size_t row = idx >> 10;
    int t = (int)(row & (TT - 1));
    int b = (int)(row >> 10);
    float cur  = xn[idx];
    float prev = t ? xn[idx - DD] : init[(size_t)b * DD + d];
    float m;
    m = mk[d]; split_store(m * cur + (1.f - m) * prev, kh, kl, idx);
    if (vh) { m = mv[d]; split_store(m * cur + (1.f - m) * prev, vh, vl, idx); }
    m = mr[d]; split_store(m * cur + (1.f - m) * prev, rh, rl, idx);
}

// ---------------- r * wkv -> bf16 hi/lo ----------------
__global__ __launch_bounds__(256)
void mul_split(const float* __restrict__ a, const float* __restrict__ b,
               __nv_bfloat16* h, __nv_bfloat16* l) {
    size_t idx = (size_t)blockIdx.x * 256 + threadIdx.x;
    split_store(a[idx] * b[idx], h, l, idx);
}

// ---------------- weight split + transpose: W[K,N] fp32 -> WT hi/lo [N,K] bf16 ----------------
__global__ __launch_bounds__(256)
void wsplit_t(const float* __restrict__ W, __nv_bfloat16* __restrict__ hi,
              __nv_bfloat16* __restrict__ lo, int Kdim, int Ndim) {
    __shared__ float t[32][33];
    int n0 = blockIdx.x * 32, k0 = blockIdx.y * 32;
    int tx = threadIdx.x, ty = threadIdx.y;
    #pragma unroll
    for (int i = ty; i < 32; i += 8)
        t[i][tx] = W[(size_t)(k0 + i) * Ndim + n0 + tx];
    __syncthreads();
    #pragma unroll
    for (int i = ty; i < 32; i += 8) {
        float v = t[tx][i];
        size_t o = (size_t)(n0 + i) * Kdim + k0 + tx;
        __nv_bfloat16 h = __float2bfloat16(v);
        hi[o] = h;
        lo[o] = __float2bfloat16(v - __bfloat162float(h));
    }
}

// ---------------- WKV scan ----------------
__global__ __launch_bounds__(64)
void wkv_scan(const float* __restrict__ kbuf, const float* __restrict__ vbuf,
              const float* __restrict__ a0, const float* __restrict__ b0,
              const float* __restrict__ p0,
              const float* __restrict__ decay, const float* __restrict__ first,
              float* __restrict__ wkvbuf,
              float* __restrict__ aa_out, float* __restrict__ bb_out,
              float* __restrict__ pp_out) {
    int idx = blockIdx.x * 64 + threadIdx.x;   // 0 .. B*D-1
    int d = idx & (DD - 1);
    int b = idx >> 10;
    float w = -__expf(decay[d]);
    float u = first[d];
    float aa = a0[idx], bb = b0[idx], pp = p0[idx];
    const float* kp = kbuf + (size_t)b * TT * DD + d;
    const float* vp = vbuf + (size_t)b * TT * DD + d;
    float* op = wkvbuf + (size_t)b * TT * DD + d;
    #pragma unroll 4
    for (int t = 0; t < TT; t++) {
        float kt = kp[(size_t)t * DD];
        float vt = vp[(size_t)t * DD];
        float ww = u + kt;
        float p  = fmaxf(pp, ww);
        float e1 = __expf(pp - p);
        float e2 = __expf(ww - p);
        op[(size_t)t * DD] = (e1 * aa + e2 * vt) / (e1 * bb + e2);
        float ww2 = pp + w;
        float p2  = fmaxf(ww2, kt);
        float e1b = __expf(ww2 - p2);
        float e2b = __expf(kt - p2);
        aa = e1b * aa + e2b * vt;
        bb = e1b * bb + e2b;
        pp = p2;
    }
    aa_out[idx] = aa; bb_out[idx] = bb; pp_out[idx] = pp;
}

// ---------------- bf16x3 mma.sync GEMM: C[M,N] = A[M,K] @ B^T (B stored [N,K]) ----------------
// CTA tile 128x128, BK=32, 8 warps (warp tile 32x64), 3-stage cp.async pipeline.
#define BKT 32
#define ROWP 80                       // smem row pitch bytes (32 bf16 + 8 pad)
#define MATB (128 * ROWP)             // 10240 B per matrix per stage
#define STAGEB (4 * MATB)             // Ah, Al, Bh, Bl
#define NSTAGE 3
#define GEMM_SMEM (NSTAGE * STAGEB)   // 122880

__device__ __forceinline__ void epi_pair(float v0, float v1, size_t base,
                                         int act,
                                         const float* __restrict__ mulp,
                                         const float* __restrict__ addp,
                                         float* __restrict__ Cf,
                                         __nv_bfloat16* __restrict__ Chi,
                                         __nv_bfloat16* __restrict__ Clo) {
    if (act == 1) {
        v0 = 1.f / (1.f + __expf(-v0));
        v1 = 1.f / (1.f + __expf(-v1));
    } else if (act == 2) {
        v0 = fmaxf(v0, 0.f); v0 *= v0;
        v1 = fmaxf(v1, 0.f); v1 *= v1;
    }
    if (mulp) { float2 m = *(const float2*)(mulp + base); v0 *= m.x; v1 *= m.y; }
    if (addp) { float2 a = *(const float2*)(addp + base); v0 += a.x; v1 += a.y; }
    if (Cf) { float2 o; o.x = v0; o.y = v1; *(float2*)(Cf + base) = o; }
    if (Chi) {
        __nv_bfloat16 h0 = __float2bfloat16(v0), h1 = __float2bfloat16(v1);
        uint32_t hp = (uint32_t)__bfloat16_as_ushort(h0)
                    | ((uint32_t)__bfloat16_as_ushort(h1) << 16);
        *(uint32_t*)(Chi + base) = hp;
        __nv_bfloat16 l0 = __float2bfloat16(v0 - __bfloat162float(h0));
        __nv_bfloat16 l1 = __float2bfloat16(v1 - __bfloat162float(h1));
        uint32_t lp = (uint32_t)__bfloat16_as_ushort(l0)
                    | ((uint32_t)__bfloat16_as_ushort(l1) << 16);
        *(uint32_t*)(Clo + base) = lp;
    }
}

__global__ __launch_bounds__(256, 1)
void mma_gemm(const __nv_bfloat16* __restrict__ Ahi, const __nv_bfloat16* __restrict__ Alo,
              const __nv_bfloat16* __restrict__ Bhi, const __nv_bfloat16* __restrict__ Blo,
              int Kn, int Nn,
              float* __restrict__ Cf,
              __nv_bfloat16* __restrict__ Chi, __nv_bfloat16* __restrict__ Clo,
              int act, const float* __restrict__ mulp, const float* __restrict__ addp) {
    extern __shared__ char sm[];
    const uint32_t sbase = smem_u32(sm);
    const int tid = threadIdx.x;
    const int lane = tid & 31, wid = tid >> 5;
    const int m0 = blockIdx.y * 128, n0 = blockIdx.x * 128;
    const int KT = Kn >> 5;
    const int wm = (wid >> 1) * 32;   // warp m offset
    const int wn = (wid & 1) * 64;    // warp n offset

    float acc[2][8][4];
    #pragma unroll
    for (int t = 0; t < 2; t++)
        #pragma unroll
        for (int j = 0; j < 8; j++)
            #pragma unroll
            for (int q = 0; q < 4; q++) acc[t][j][q] = 0.f;

    auto issue = [&](int kt) {
        const int slot = kt % NSTAGE;
        const uint32_t st = sbase + slot * STAGEB;
        const size_t k0 = (size_t)kt << 5;
        #pragma unroll
        for (int h = 0; h < 2; h++) {
            int idx = tid + h * 256;        // 0..511
            int row = idx >> 2, ch = idx & 3;
            uint32_t doff = (uint32_t)row * ROWP + ch * 16;
            size_t aoff = (size_t)(m0 + row) * Kn + k0 + ch * 8;
            size_t boff = (size_t)(n0 + row) * Kn + k0 + ch * 8;
            cpa16(st + doff,            Ahi + aoff);
            cpa16(st + MATB + doff,     Alo + aoff);
            cpa16(st + 2 * MATB + doff, Bhi + boff);
            cpa16(st + 3 * MATB + doff, Blo + boff);
        }
        CP_COMMIT();
    };

    issue(0);
    issue(1);

    for (int kt = 0; kt < KT; kt++) {
        CP_WAIT(1);
        __syncthreads();
        const uint32_t st = sbase + (kt % NSTAGE) * STAGEB;
        #pragma unroll
        for (int ks = 0; ks < 2; ks++) {
            const int k0 = ks * 16;
            uint32_t ah[2][4], al[2][4], bh[8][2], bl[8][2];
            #pragma unroll
            for (int t = 0; t < 2; t++) {
                uint32_t ad = st + (uint32_t)(wm + t * 16 + (lane & 15)) * ROWP
                            + (k0 + (lane >> 4) * 8) * 2;
                ldsm4(ah[t], ad);
                ldsm4(al[t], ad + MATB);
            }
            #pragma unroll
            for (int p = 0; p < 4; p++) {
                int g = lane >> 3, r = lane & 7;
                int n = wn + (p * 2 + (g >> 1)) * 8 + r;
                int k = k0 + (g & 1) * 8;
                uint32_t bd = st + 2 * MATB + (uint32_t)n * ROWP + k * 2;
                ldsm4(&bh[p * 2][0], bd);
                ldsm4(&bl[p * 2][0], bd + MATB);
            }
            #pragma unroll
            for (int t = 0; t < 2; t++)
                #pragma unroll
                for (int j = 0; j < 8; j++)
                    mma_bf16(acc[t][j], ah[t], bh[j]);
            #pragma unroll
            for (int t = 0; t < 2; t++)
                #pragma unroll
                for (int j = 0; j < 8; j++)
                    mma_bf16(acc[t][j], ah[t], bl[j]);
            #pragma unroll
            for (int t = 0; t < 2; t++)
                #pragma unroll
                for (int j = 0; j < 8; j++)
                    mma_bf16(acc[t][j], al[t], bh[j]);
        }
        if (kt + 2 < KT) issue(kt + 2);
    }
    CP_WAIT(0);

    // ---- epilogue ----
    #pragma unroll
    for (int t = 0; t < 2; t++) {
        int row = m0 + wm + t * 16 + (lane >> 2);
        #pragma unroll
        for (int j = 0; j < 8; j++) {
            int col = n0 + wn + j * 8 + ((lane & 3) << 1);
            size_t b0 = (size_t)row * Nn + col;
            size_t b1 = (size_t)(row + 8) * Nn + col;
            epi_pair(acc[t][j][0], acc[t][j][1], b0, act, mulp, addp, Cf, Chi, Clo);
            epi_pair(acc[t][j][2], acc[t][j][3], b1, act, mulp, addp, Cf, Chi, Clo);
        }
    }
}

// ---------------- host driver ----------------
extern "C" void kernel_launch(void* const* d_in, const int* in_sizes, int n_in,
                              void* d_out, int out_size) {
    const float* x        = (const float*)d_in[0];
    const float* att_x    = (const float*)d_in[1];
    const float* att_a    = (const float*)d_in[2];
    const float* att_b    = (const float*)d_in[3];
    const float* att_p    = (const float*)d_in[4];
    const float* ffn_x    = (const float*)d_in[5];
    const float* ln1_g    = (const float*)d_in[6];
    const float* ln1_b    = (const float*)d_in[7];
    const float* ln2_g    = (const float*)d_in[8];
    const float* ln2_b    = (const float*)d_in[9];
    const float* tm_mix_k = (const float*)d_in[10];
    const float* tm_mix_v = (const float*)d_in[11];
    const float* tm_mix_r = (const float*)d_in[12];
    const float* tm_decay = (const float*)d_in[13];
    const float* tm_first = (const float*)d_in[14];
    const float* Wk       = (const float*)d_in[15];
    const float* Wv       = (const float*)d_in[16];
    const float* Wr       = (const float*)d_in[17];
    const float* Wo       = (const float*)d_in[18];
    const float* cm_mix_k = (const float*)d_in[19];
    const float* cm_mix_r = (const float*)d_in[20];
    const float* Ck       = (const float*)d_in[21];
    const float* Cr       = (const float*)d_in[22];
    const float* Cv       = (const float*)d_in[23];

    float* out      = (float*)d_out;
    float* xn_last  = out + (size_t)MM * DD;
    float* aa_out   = xn_last  + (size_t)BB * DD;
    float* bb_out   = aa_out   + (size_t)BB * DD;
    float* pp_out   = bb_out   + (size_t)BB * DD;
    float* xn2_last = pp_out   + (size_t)BB * DD;

    float *xn, *kb, *vb, *rb, *wkv, *x1, *xn2, *rc;
    __nv_bfloat16 *akh, *akl, *avh, *avl, *arh, *arl, *kch, *kcl;
    __nv_bfloat16 *wkh, *wkl, *wvh, *wvl, *wrh, *wrl, *woh, *wol;
    __nv_bfloat16 *crh, *crl, *ckh, *ckl, *cvh, *cvl;
    cudaGetSymbolAddress((void**)&xn,  g_xn);
    cudaGetSymbolAddress((void**)&kb,  g_kb);
    cudaGetSymbolAddress((void**)&vb,  g_vb);
    cudaGetSymbolAddress((void**)&rb,  g_rb);
    cudaGetSymbolAddress((void**)&wkv, g_wkv);
    cudaGetSymbolAddress((void**)&x1,  g_x1);
    cudaGetSymbolAddress((void**)&xn2, g_xn2);
    cudaGetSymbolAddress((void**)&rc,  g_rc);
    cudaGetSymbolAddress((void**)&akh, g_akh);
    cudaGetSymbolAddress((void**)&akl, g_akl);
    cudaGetSymbolAddress((void**)&avh, g_avh);
    cudaGetSymbolAddress((void**)&avl, g_avl);
    cudaGetSymbolAddress((void**)&arh, g_arh);
    cudaGetSymbolAddress((void**)&arl, g_arl);
    cudaGetSymbolAddress((void**)&kch, g_kch);
    cudaGetSymbolAddress((void**)&kcl, g_kcl);
    cudaGetSymbolAddress((void**)&wkh, g_wkh); cudaGetSymbolAddress((void**)&wkl, g_wkl);
    cudaGetSymbolAddress((void**)&wvh, g_wvh); cudaGetSymbolAddress((void**)&wvl, g_wvl);
    cudaGetSymbolAddress((void**)&wrh, g_wrh); cudaGetSymbolAddress((void**)&wrl, g_wrl);
    cudaGetSymbolAddress((void**)&woh, g_woh); cudaGetSymbolAddress((void**)&wol, g_wol);
    cudaGetSymbolAddress((void**)&crh, g_crh); cudaGetSymbolAddress((void**)&crl, g_crl);
    cudaGetSymbolAddress((void**)&ckh, g_ckh); cudaGetSymbolAddress((void**)&ckl, g_ckl);
    cudaGetSymbolAddress((void**)&cvh, g_cvh); cudaGetSymbolAddress((void**)&cvl, g_cvl);

    cudaFuncSetAttribute(mma_gemm, cudaFuncAttributeMaxDynamicSharedMemorySize, GEMM_SMEM);

    const int ELT_BLOCKS = (int)(((size_t)MM * DD) / 256);  // 32768
    dim3 wt_thr(32, 8);

    // ---- weight conversion (split + transpose) ----
    wsplit_t<<<dim3(DD/32, DD/32), wt_thr>>>(Wk, wkh, wkl, DD, DD);
    wsplit_t<<<dim3(DD/32, DD/32), wt_thr>>>(Wv, wvh, wvl, DD, DD);
    wsplit_t<<<dim3(DD/32, DD/32), wt_thr>>>(Wr, wrh, wrl, DD, DD);
    wsplit_t<<<dim3(DD/32, DD/32), wt_thr>>>(Wo, woh, wol, DD, DD);
    wsplit_t<<<dim3(DD/32, DD/32), wt_thr>>>(Cr, crh, crl, DD, DD);
    wsplit_t<<<dim3(FF/32, DD/32), wt_thr>>>(Ck, ckh, ckl, DD, FF);  // -> [FF,DD]
    wsplit_t<<<dim3(DD/32, FF/32), wt_thr>>>(Cv, cvh, cvl, FF, DD);  // -> [DD,FF]

    dim3 g1k(DD / 128, MM / 128);   // (8, 64)
    dim3 g4k(FF / 128, MM / 128);   // (32, 64)

    // ---- time mixing ----
    ln_kernel<<<MM, 256>>>(x, ln1_g, ln1_b, xn, xn_last);
    mix_split<<<ELT_BLOCKS, 256>>>(xn, att_x, tm_mix_k, tm_mix_v, tm_mix_r,
                                   akh, akl, avh, avl, arh, arl);
    mma_gemm<<<g1k, 256, GEMM_SMEM>>>(akh, akl, wkh, wkl, DD, DD,
                                      kb, nullptr, nullptr, 0, nullptr, nullptr);
    mma_gemm<<<g1k, 256, GEMM_SMEM>>>(avh, avl, wvh, wvl, DD, DD,
                                      vb, nullptr, nullptr, 0, nullptr, nullptr);
    mma_gemm<<<g1k, 256, GEMM_SMEM>>>(arh, arl, wrh, wrl, DD, DD,
                                      rb, nullptr, nullptr, 1, nullptr, nullptr);

    wkv_scan<<<(BB * DD) / 64, 64>>>(kb, vb, att_a, att_b, att_p,
                                     tm_decay, tm_first, wkv,
                                     aa_out, bb_out, pp_out);

    mul_split<<<ELT_BLOCKS, 256>>>(rb, wkv, avh, avl);   // r * wkv -> bf16 split
    mma_gemm<<<g1k, 256, GEMM_SMEM>>>(avh, avl, woh, wol, DD, DD,
                                      x1, nullptr, nullptr, 0, nullptr, x);

    // ---- channel mixing ----
    ln_kernel<<<MM, 256>>>(x1, ln2_g, ln2_b, xn2, xn2_last);
    mix_split<<<ELT_BLOCKS, 256>>>(xn2, ffn_x, cm_mix_k, nullptr, cm_mix_r,
                                   akh, akl, nullptr, nullptr, arh, arl);
    mma_gemm<<<g4k, 256, GEMM_SMEM>>>(akh, akl, ckh, ckl, DD, FF,
                                      nullptr, kch, kcl, 2, nullptr, nullptr);
    mma_gemm<<<g1k, 256, GEMM_SMEM>>>(arh, arl, crh, crl, DD, DD,
                                      rc, nullptr, nullptr, 1, nullptr, nullptr);
    mma_gemm<<<g1k, 256, GEMM_SMEM>>>(kch, kcl, cvh, cvl, FF, DD,
                                      out, nullptr, nullptr, 0, rc, x1);
}

// round 7
// speedup vs baseline: 3.0293x; 1.2851x over previous
#include <cuda_runtime.h>
#include <cuda_fp16.h>
#include <cuda_bf16.h>
#include <cstdint>

// ---------------- problem constants ----------------
#define BB 8
#define TT 1024
#define DD 1024
#define FF 4096
#define MM (BB * TT)          // 8192 rows
#define EPS_LN 1e-3f

// ---------------- PTX helpers ----------------
__device__ __forceinline__ uint32_t smem_u32(const void* p) {
    uint32_t a;
    asm("{ .reg .u64 t; cvta.to.shared.u64 t, %1; cvt.u32.u64 %0, t; }"
        : "=r"(a) : "l"(p));
    return a;
}

__device__ __forceinline__ void cpa16(uint32_t dst, const void* src) {
    asm volatile("cp.async.cg.shared.global [%0], [%1], 16;"
                 :: "r"(dst), "l"(src) : "memory");
}
#define CP_COMMIT() asm volatile("cp.async.commit_group;" ::: "memory")
#define CP_WAIT(n)  asm volatile("cp.async.wait_group %0;" :: "n"(n) : "memory")

__device__ __forceinline__ void ldsm4(uint32_t* r, uint32_t a) {
    asm volatile("ldmatrix.sync.aligned.m8n8.x4.shared.b16 {%0,%1,%2,%3}, [%4];"
                 : "=r"(r[0]), "=r"(r[1]), "=r"(r[2]), "=r"(r[3]) : "r"(a));
}

__device__ __forceinline__ void mma_fp16(float* c, const uint32_t* a, const uint32_t* b) {
    asm volatile(
        "mma.sync.aligned.m16n8k16.row.col.f32.f16.f16.f32 "
        "{%0,%1,%2,%3}, {%4,%5,%6,%7}, {%8,%9}, {%0,%1,%2,%3};"
        : "+f"(c[0]), "+f"(c[1]), "+f"(c[2]), "+f"(c[3])
        : "r"(a[0]), "r"(a[1]), "r"(a[2]), "r"(a[3]), "r"(b[0]), "r"(b[1]));
}

// ---------------- scratch (static device globals) ----------------
__device__ float g_xn [(size_t)MM * DD];
__device__ float g_kb [(size_t)MM * DD];
__device__ float g_vb [(size_t)MM * DD];
__device__ float g_rb [(size_t)MM * DD];
__device__ float g_wkv[(size_t)MM * DD];
__device__ float g_x1 [(size_t)MM * DD];
__device__ float g_xn2[(size_t)MM * DD];
__device__ float g_rc [(size_t)MM * DD];
// fp16 activations (single precision copy; weights carry the split)
__device__ __half g_ak[(size_t)MM * DD];
__device__ __half g_av[(size_t)MM * DD];
__device__ __half g_ar[(size_t)MM * DD];
__device__ __half g_kc[(size_t)MM * FF];
// fp16 transposed weight splits [N, K]
__device__ __half g_wkh[(size_t)DD * DD], g_wkl[(size_t)DD * DD];
__device__ __half g_wvh[(size_t)DD * DD], g_wvl[(size_t)DD * DD];
__device__ __half g_wrh[(size_t)DD * DD], g_wrl[(size_t)DD * DD];
__device__ __half g_woh[(size_t)DD * DD], g_wol[(size_t)DD * DD];
__device__ __half g_crh[(size_t)DD * DD], g_crl[(size_t)DD * DD];
__device__ __half g_ckh[(size_t)FF * DD], g_ckl[(size_t)FF * DD];   // Ck^T
__device__ __half g_cvh[(size_t)DD * FF], g_cvl[(size_t)DD * FF];   // Cv^T

// ---------------- LayerNorm ----------------
__global__ __launch_bounds__(256)
void ln_kernel(const float* __restrict__ x, const float* __restrict__ gamma,
               const float* __restrict__ beta, float* __restrict__ y,
               float* __restrict__ last_out) {
    __shared__ float red0[8], red1[8];
    int row = blockIdx.x;
    const float* xr = x + (size_t)row * DD;
    float s = 0.f, s2 = 0.f;
    #pragma unroll
    for (int i = threadIdx.x; i < DD; i += 256) {
        float v = xr[i];
        s += v; s2 += v * v;
    }
    #pragma unroll
    for (int o = 16; o; o >>= 1) {
        s  += __shfl_down_sync(0xffffffffu, s,  o);
        s2 += __shfl_down_sync(0xffffffffu, s2, o);
    }
    int lane = threadIdx.x & 31, wid = threadIdx.x >> 5;
    if (lane == 0) { red0[wid] = s; red1[wid] = s2; }
    __syncthreads();
    s = 0.f; s2 = 0.f;
    #pragma unroll
    for (int i = 0; i < 8; i++) { s += red0[i]; s2 += red1[i]; }
    const float invD = 1.0f / DD;
    float mu  = s * invD;
    float var = s2 * invD - mu * mu;
    float inv = rsqrtf(var + EPS_LN);
    float* yr = y + (size_t)row * DD;
    bool is_last = ((row & (TT - 1)) == (TT - 1));
    float* lr = last_out + (size_t)(row >> 10) * DD;
    #pragma unroll
    for (int i = threadIdx.x; i < DD; i += 256) {
        float v = (xr[i] - mu) * inv * gamma[i] + beta[i];
        yr[i] = v;
        if (is_last) lr[i] = v;
    }
}

// ---------------- token-shift mix -> fp16 ----------------
__global__ __launch_bounds__(256)
void mix_h(const float* __restrict__ xn, const float* __restrict__ init,
           const float* __restrict__ mk, const float* __restrict__ mv,
           const float* __restrict__ mr,
           __half* __restrict__ ok, __half* __restrict__ ov,
           __half* __restrict__ orr) {
    size_t idx = (size_t)blockIdx.x * 256 + threadIdx.x;
    int d = (int)(idx & (DD - 1));
    size_t row = idx >> 10;
    int t = (int)(row & (TT - 1));
    int b = (int)(row >> 10);
    float cur  = xn[idx];
    float prev = t ? xn[idx - DD] : init[(size_t)b * DD + d];
    float m;
    m = mk[d]; ok[idx]  = __float2half(m * cur + (1.f - m) * prev);
    if (ov) { m = mv[d]; ov[idx] = __float2half(m * cur + (1.f - m) * prev); }
    m = mr[d]; orr[idx] = __float2half(m * cur + (1.f - m) * prev);
}

// ---------------- r * wkv -> fp16 ----------------
__global__ __launch_bounds__(256)
void mul_h(const float* __restrict__ a, const float* __restrict__ b,
           __half* __restrict__ o) {
    size_t idx = (size_t)blockIdx.x * 256 + threadIdx.x;
    o[idx] = __float2half(a[idx] * b[idx]);
}

// ---------------- weight split + transpose: W[K,N] fp32 -> WT hi/lo [N,K] fp16 ----------------
__global__ __launch_bounds__(256)
void wsplit_t(const float* __restrict__ W, __half* __restrict__ hi,
              __half* __restrict__ lo, int Kdim, int Ndim) {
    __shared__ float t[32][33];
    int n0 = blockIdx.x * 32, k0 = blockIdx.y * 32;
    int tx = threadIdx.x, ty = threadIdx.y;
    #pragma unroll
    for (int i = ty; i < 32; i += 8)
        t[i][tx] = W[(size_t)(k0 + i) * Ndim + n0 + tx];
    __syncthreads();
    #pragma unroll
    for (int i = ty; i < 32; i += 8) {
        float v = t[tx][i];
        size_t o = (size_t)(n0 + i) * Kdim + k0 + tx;
        __half h = __float2half(v);
        hi[o] = h;
        lo[o] = __float2half(v - __half2float(h));
    }
}

// ---------------- WKV scan ----------------
__global__ __launch_bounds__(64)
void wkv_scan(const float* __restrict__ kbuf, const float* __restrict__ vbuf,
              const float* __restrict__ a0, const float* __restrict__ b0,
              const float* __restrict__ p0,
              const float* __restrict__ decay, const float* __restrict__ first,
              float* __restrict__ wkvbuf,
              float* __restrict__ aa_out, float* __restrict__ bb_out,
              float* __restrict__ pp_out) {
    int idx = blockIdx.x * 64 + threadIdx.x;   // 0 .. B*D-1
    int d = idx & (DD - 1);
    int b = idx >> 10;
    float w = -__expf(decay[d]);
    float u = first[d];
    float aa = a0[idx], bb = b0[idx], pp = p0[idx];
    const float* kp = kbuf + (size_t)b * TT * DD + d;
    const float* vp = vbuf + (size_t)b * TT * DD + d;
    float* op = wkvbuf + (size_t)b * TT * DD + d;
    #pragma unroll 4
    for (int t = 0; t < TT; t++) {
        float kt = kp[(size_t)t * DD];
        float vt = vp[(size_t)t * DD];
        float ww = u + kt;
        float p  = fmaxf(pp, ww);
        float e1 = __expf(pp - p);
        float e2 = __expf(ww - p);
        op[(size_t)t * DD] = (e1 * aa + e2 * vt) / (e1 * bb + e2);
        float ww2 = pp + w;
        float p2  = fmaxf(ww2, kt);
        float e1b = __expf(ww2 - p2);
        float e2b = __expf(kt - p2);
        aa = e1b * aa + e2b * vt;
        bb = e1b * bb + e2b;
        pp = p2;
    }
    aa_out[idx] = aa; bb_out[idx] = bb; pp_out[idx] = pp;
}

// ---------------- fp16 x2 mma.sync GEMM: C[M,N] = A[M,K] @ (Wh+Wl)^T (W stored [N,K]) ----------------
// CTA tile 128x128, BK=32, 8 warps (warp tile 32x64), 4-stage cp.async pipeline.
#define ROWP 80                       // smem row pitch bytes (32 fp16 + 8 pad)
#define MATB (128 * ROWP)             // 10240 B per matrix per stage
#define STAGEB (3 * MATB)             // A, Bh, Bl
#define NSTAGE 4
#define GEMM_SMEM (NSTAGE * STAGEB)   // 122880

__device__ __forceinline__ void epi_pair(float v0, float v1, size_t base,
                                         int act,
                                         const float* __restrict__ mulp,
                                         const float* __restrict__ addp,
                                         float* __restrict__ Cf,
                                         __half* __restrict__ Ch) {
    if (act == 1) {
        v0 = 1.f / (1.f + __expf(-v0));
        v1 = 1.f / (1.f + __expf(-v1));
    } else if (act == 2) {
        v0 = fmaxf(v0, 0.f); v0 *= v0;
        v1 = fmaxf(v1, 0.f); v1 *= v1;
    }
    if (mulp) { float2 m = *(const float2*)(mulp + base); v0 *= m.x; v1 *= m.y; }
    if (addp) { float2 a = *(const float2*)(addp + base); v0 += a.x; v1 += a.y; }
    if (Cf) { float2 o; o.x = v0; o.y = v1; *(float2*)(Cf + base) = o; }
    if (Ch) {
        __half2 h = __floats2half2_rn(v0, v1);
        *(__half2*)(Ch + base) = h;
    }
}

__global__ __launch_bounds__(256, 1)
void mma_gemm(const __half* __restrict__ A,
              const __half* __restrict__ Bhi, const __half* __restrict__ Blo,
              int Kn, int Nn,
              float* __restrict__ Cf, __half* __restrict__ Ch,
              int act, const float* __restrict__ mulp, const float* __restrict__ addp) {
    extern __shared__ char sm[];
    const uint32_t sbase = smem_u32(sm);
    const int tid = threadIdx.x;
    const int lane = tid & 31, wid = tid >> 5;
    const int m0 = blockIdx.y * 128, n0 = blockIdx.x * 128;
    const int KT = Kn >> 5;
    const int wm = (wid >> 1) * 32;   // warp m offset
    const int wn = (wid & 1) * 64;    // warp n offset

    float acc[2][8][4];
    #pragma unroll
    for (int t = 0; t < 2; t++)
        #pragma unroll
        for (int j = 0; j < 8; j++)
            #pragma unroll
            for (int q = 0; q < 4; q++) acc[t][j][q] = 0.f;

    auto issue = [&](int kt) {
        const int slot = kt % NSTAGE;
        const uint32_t st = sbase + slot * STAGEB;
        const size_t k0 = (size_t)kt << 5;
        #pragma unroll
        for (int h = 0; h < 2; h++) {
            int idx = tid + h * 256;        // 0..511
            int row = idx >> 2, ch = idx & 3;
            uint32_t doff = (uint32_t)row * ROWP + ch * 16;
            size_t aoff = (size_t)(m0 + row) * Kn + k0 + ch * 8;
            size_t boff = (size_t)(n0 + row) * Kn + k0 + ch * 8;
            cpa16(st + doff,            A   + aoff);
            cpa16(st + MATB + doff,     Bhi + boff);
            cpa16(st + 2 * MATB + doff, Blo + boff);
        }
        CP_COMMIT();
    };

    issue(0);
    issue(1);
    issue(2);

    for (int kt = 0; kt < KT; kt++) {
        CP_WAIT(2);
        __syncthreads();
        const uint32_t st = sbase + (kt % NSTAGE) * STAGEB;
        #pragma unroll
        for (int ks = 0; ks < 2; ks++) {
            const int k0 = ks * 16;
            uint32_t ah[2][4], bh[8][2], bl[8][2];
            #pragma unroll
            for (int t = 0; t < 2; t++) {
                uint32_t ad = st + (uint32_t)(wm + t * 16 + (lane & 15)) * ROWP
                            + (k0 + (lane >> 4) * 8) * 2;
                ldsm4(ah[t], ad);
            }
            #pragma unroll
            for (int p = 0; p < 4; p++) {
                int g = lane >> 3, r = lane & 7;
                int n = wn + (p * 2 + (g >> 1)) * 8 + r;
                int k = k0 + (g & 1) * 8;
                uint32_t bd = st + MATB + (uint32_t)n * ROWP + k * 2;
                ldsm4(&bh[p * 2][0], bd);
                ldsm4(&bl[p * 2][0], bd + MATB);
            }
            #pragma unroll
            for (int t = 0; t < 2; t++)
                #pragma unroll
                for (int j = 0; j < 8; j++)
                    mma_fp16(acc[t][j], ah[t], bh[j]);
            #pragma unroll
            for (int t = 0; t < 2; t++)
                #pragma unroll
                for (int j = 0; j < 8; j++)
                    mma_fp16(acc[t][j], ah[t], bl[j]);
        }
        if (kt + 3 < KT) issue(kt + 3);
    }
    CP_WAIT(0);

    // ---- epilogue ----
    #pragma unroll
    for (int t = 0; t < 2; t++) {
        int row = m0 + wm + t * 16 + (lane >> 2);
        #pragma unroll
        for (int j = 0; j < 8; j++) {
            int col = n0 + wn + j * 8 + ((lane & 3) << 1);
            size_t b0 = (size_t)row * Nn + col;
            size_t b1 = (size_t)(row + 8) * Nn + col;
            epi_pair(acc[t][j][0], acc[t][j][1], b0, act, mulp, addp, Cf, Ch);
            epi_pair(acc[t][j][2], acc[t][j][3], b1, act, mulp, addp, Cf, Ch);
        }
    }
}

// ---------------- host driver ----------------
extern "C" void kernel_launch(void* const* d_in, const int* in_sizes, int n_in,
                              void* d_out, int out_size) {
    const float* x        = (const float*)d_in[0];
    const float* att_x    = (const float*)d_in[1];
    const float* att_a    = (const float*)d_in[2];
    const float* att_b    = (const float*)d_in[3];
    const float* att_p    = (const float*)d_in[4];
    const float* ffn_x    = (const float*)d_in[5];
    const float* ln1_g    = (const float*)d_in[6];
    const float* ln1_b    = (const float*)d_in[7];
    const float* ln2_g    = (const float*)d_in[8];
    const float* ln2_b    = (const float*)d_in[9];
    const float* tm_mix_k = (const float*)d_in[10];
    const float* tm_mix_v = (const float*)d_in[11];
    const float* tm_mix_r = (const float*)d_in[12];
    const float* tm_decay = (const float*)d_in[13];
    const float* tm_first = (const float*)d_in[14];
    const float* Wk       = (const float*)d_in[15];
    const float* Wv       = (const float*)d_in[16];
    const float* Wr       = (const float*)d_in[17];
    const float* Wo       = (const float*)d_in[18];
    const float* cm_mix_k = (const float*)d_in[19];
    const float* cm_mix_r = (const float*)d_in[20];
    const float* Ck       = (const float*)d_in[21];
    const float* Cr       = (const float*)d_in[22];
    const float* Cv       = (const float*)d_in[23];

    float* out      = (float*)d_out;
    float* xn_last  = out + (size_t)MM * DD;
    float* aa_out   = xn_last  + (size_t)BB * DD;
    float* bb_out   = aa_out   + (size_t)BB * DD;
    float* pp_out   = bb_out   + (size_t)BB * DD;
    float* xn2_last = pp_out   + (size_t)BB * DD;

    float *xn, *kb, *vb, *rb, *wkv, *x1, *xn2, *rc;
    __half *ak, *av, *ar, *kc;
    __half *wkh, *wkl, *wvh, *wvl, *wrh, *wrl, *woh, *wol;
    __half *crh, *crl, *ckh, *ckl, *cvh, *cvl;
    cudaGetSymbolAddress((void**)&xn,  g_xn);
    cudaGetSymbolAddress((void**)&kb,  g_kb);
    cudaGetSymbolAddress((void**)&vb,  g_vb);
    cudaGetSymbolAddress((void**)&rb,  g_rb);
    cudaGetSymbolAddress((void**)&wkv, g_wkv);
    cudaGetSymbolAddress((void**)&x1,  g_x1);
    cudaGetSymbolAddress((void**)&xn2, g_xn2);
    cudaGetSymbolAddress((void**)&rc,  g_rc);
    cudaGetSymbolAddress((void**)&ak,  g_ak);
    cudaGetSymbolAddress((void**)&av,  g_av);
    cudaGetSymbolAddress((void**)&ar,  g_ar);
    cudaGetSymbolAddress((void**)&kc,  g_kc);
    cudaGetSymbolAddress((void**)&wkh, g_wkh); cudaGetSymbolAddress((void**)&wkl, g_wkl);
    cudaGetSymbolAddress((void**)&wvh, g_wvh); cudaGetSymbolAddress((void**)&wvl, g_wvl);
    cudaGetSymbolAddress((void**)&wrh, g_wrh); cudaGetSymbolAddress((void**)&wrl, g_wrl);
    cudaGetSymbolAddress((void**)&woh, g_woh); cudaGetSymbolAddress((void**)&wol, g_wol);
    cudaGetSymbolAddress((void**)&crh, g_crh); cudaGetSymbolAddress((void**)&crl, g_crl);
    cudaGetSymbolAddress((void**)&ckh, g_ckh); cudaGetSymbolAddress((void**)&ckl, g_ckl);
    cudaGetSymbolAddress((void**)&cvh, g_cvh); cudaGetSymbolAddress((void**)&cvl, g_cvl);

    cudaFuncSetAttribute(mma_gemm, cudaFuncAttributeMaxDynamicSharedMemorySize, GEMM_SMEM);

    const int ELT_BLOCKS = (int)(((size_t)MM * DD) / 256);  // 32768
    dim3 wt_thr(32, 8);
    dim3 g1k(DD / 128, MM / 128);   // (8, 64)
    dim3 g4k(FF / 128, MM / 128);   // (32, 64)

    // ---- time mixing ----
    // launch order puts the Wk GEMM at index 5 so ncu (-s 5 -c 1) captures it
    wsplit_t<<<dim3(DD/32, DD/32), wt_thr>>>(Wk, wkh, wkl, DD, DD);           // 0
    wsplit_t<<<dim3(DD/32, DD/32), wt_thr>>>(Wv, wvh, wvl, DD, DD);           // 1
    wsplit_t<<<dim3(DD/32, DD/32), wt_thr>>>(Wr, wrh, wrl, DD, DD);           // 2
    ln_kernel<<<MM, 256>>>(x, ln1_g, ln1_b, xn, xn_last);                     // 3
    mix_h<<<ELT_BLOCKS, 256>>>(xn, att_x, tm_mix_k, tm_mix_v, tm_mix_r,
                               ak, av, ar);                                   // 4
    mma_gemm<<<g1k, 256, GEMM_SMEM>>>(ak, wkh, wkl, DD, DD,
                                      kb, nullptr, 0, nullptr, nullptr);      // 5 <- profiled
    mma_gemm<<<g1k, 256, GEMM_SMEM>>>(av, wvh, wvl, DD, DD,
                                      vb, nullptr, 0, nullptr, nullptr);
    mma_gemm<<<g1k, 256, GEMM_SMEM>>>(ar, wrh, wrl, DD, DD,
                                      rb, nullptr, 1, nullptr, nullptr);

    wkv_scan<<<(BB * DD) / 64, 64>>>(kb, vb, att_a, att_b, att_p,
                                     tm_decay, tm_first, wkv,
                                     aa_out, bb_out, pp_out);

    wsplit_t<<<dim3(DD/32, DD/32), wt_thr>>>(Wo, woh, wol, DD, DD);
    mul_h<<<ELT_BLOCKS, 256>>>(rb, wkv, av);            // av := fp16(r * wkv)
    mma_gemm<<<g1k, 256, GEMM_SMEM>>>(av, woh, wol, DD, DD,
                                      x1, nullptr, 0, nullptr, x);

    // ---- channel mixing ----
    wsplit_t<<<dim3(DD/32, DD/32), wt_thr>>>(Cr, crh, crl, DD, DD);
    wsplit_t<<<dim3(FF/32, DD/32), wt_thr>>>(Ck, ckh, ckl, DD, FF);  // -> [FF,DD]
    wsplit_t<<<dim3(DD/32, FF/32), wt_thr>>>(Cv, cvh, cvl, FF, DD);  // -> [DD,FF]
    ln_kernel<<<MM, 256>>>(x1, ln2_g, ln2_b, xn2, xn2_last);
    mix_h<<<ELT_BLOCKS, 256>>>(xn2, ffn_x, cm_mix_k, nullptr, cm_mix_r,
                               ak, nullptr, ar);
    mma_gemm<<<g4k, 256, GEMM_SMEM>>>(ak, ckh, ckl, DD, FF,
                                      nullptr, kc, 2, nullptr, nullptr);  // relu^2 -> fp16
    mma_gemm<<<g1k, 256, GEMM_SMEM>>>(ar, crh, crl, DD, DD,
                                      rc, nullptr, 1, nullptr, nullptr);
    mma_gemm<<<g1k, 256, GEMM_SMEM>>>(kc, cvh, cvl, FF, DD,
                                      out, nullptr, 0, rc, x1);
}

// round 8
// speedup vs baseline: 3.5344x; 1.1668x over previous
#include <cuda_runtime.h>
#include <cuda_fp16.h>
#include <cuda_bf16.h>
#include <cstdint>

// ---------------- problem constants ----------------
#define BB 8
#define TT 1024
#define DD 1024
#define FF 4096
#define MM (BB * TT)          // 8192 rows
#define EPS_LN 1e-3f

// ---------------- PTX helpers ----------------
__device__ __forceinline__ uint32_t smem_u32(const void* p) {
    uint32_t a;
    asm("{ .reg .u64 t; cvta.to.shared.u64 t, %1; cvt.u32.u64 %0, t; }"
        : "=r"(a) : "l"(p));
    return a;
}

__device__ __forceinline__ void cpa16(uint32_t dst, const void* src) {
    asm volatile("cp.async.cg.shared.global [%0], [%1], 16;"
                 :: "r"(dst), "l"(src) : "memory");
}
#define CP_COMMIT() asm volatile("cp.async.commit_group;" ::: "memory")
#define CP_WAIT(n)  asm volatile("cp.async.wait_group %0;" :: "n"(n) : "memory")

__device__ __forceinline__ void ldsm4(uint32_t* r, uint32_t a) {
    asm volatile("ldmatrix.sync.aligned.m8n8.x4.shared.b16 {%0,%1,%2,%3}, [%4];"
                 : "=r"(r[0]), "=r"(r[1]), "=r"(r[2]), "=r"(r[3]) : "r"(a));
}

__device__ __forceinline__ void mma_fp16(float* c, const uint32_t* a, const uint32_t* b) {
    asm volatile(
        "mma.sync.aligned.m16n8k16.row.col.f32.f16.f16.f32 "
        "{%0,%1,%2,%3}, {%4,%5,%6,%7}, {%8,%9}, {%0,%1,%2,%3};"
        : "+f"(c[0]), "+f"(c[1]), "+f"(c[2]), "+f"(c[3])
        : "r"(a[0]), "r"(a[1]), "r"(a[2]), "r"(a[3]), "r"(b[0]), "r"(b[1]));
}

// ---------------- scratch (static device globals) ----------------
__device__ float g_xn [(size_t)MM * DD];
__device__ float g_kb [(size_t)MM * DD];
__device__ float g_vb [(size_t)MM * DD];
__device__ float g_rb [(size_t)MM * DD];
__device__ float g_wkv[(size_t)MM * DD];
__device__ float g_x1 [(size_t)MM * DD];
__device__ float g_xn2[(size_t)MM * DD];
__device__ float g_rc [(size_t)MM * DD];
// fp16 activations (single precision copy; weights carry the split)
__device__ __half g_ak[(size_t)MM * DD];
__device__ __half g_av[(size_t)MM * DD];
__device__ __half g_ar[(size_t)MM * DD];
__device__ __half g_kc[(size_t)MM * FF];
// fp16 transposed weight splits [N, K]
__device__ __half g_wkh[(size_t)DD * DD], g_wkl[(size_t)DD * DD];
__device__ __half g_wvh[(size_t)DD * DD], g_wvl[(size_t)DD * DD];
__device__ __half g_wrh[(size_t)DD * DD], g_wrl[(size_t)DD * DD];
__device__ __half g_woh[(size_t)DD * DD], g_wol[(size_t)DD * DD];
__device__ __half g_crh[(size_t)DD * DD], g_crl[(size_t)DD * DD];
__device__ __half g_ckh[(size_t)FF * DD], g_ckl[(size_t)FF * DD];   // Ck^T
__device__ __half g_cvh[(size_t)DD * FF], g_cvl[(size_t)DD * FF];   // Cv^T

// ---------------- LayerNorm ----------------
__global__ __launch_bounds__(256)
void ln_kernel(const float* __restrict__ x, const float* __restrict__ gamma,
               const float* __restrict__ beta, float* __restrict__ y,
               float* __restrict__ last_out) {
    __shared__ float red0[8], red1[8];
    int row = blockIdx.x;
    const float* xr = x + (size_t)row * DD;
    float s = 0.f, s2 = 0.f;
    #pragma unroll
    for (int i = threadIdx.x; i < DD; i += 256) {
        float v = xr[i];
        s += v; s2 += v * v;
    }
    #pragma unroll
    for (int o = 16; o; o >>= 1) {
        s  += __shfl_down_sync(0xffffffffu, s,  o);
        s2 += __shfl_down_sync(0xffffffffu, s2, o);
    }
    int lane = threadIdx.x & 31, wid = threadIdx.x >> 5;
    if (lane == 0) { red0[wid] = s; red1[wid] = s2; }
    __syncthreads();
    s = 0.f; s2 = 0.f;
    #pragma unroll
    for (int i = 0; i < 8; i++) { s += red0[i]; s2 += red1[i]; }
    const float invD = 1.0f / DD;
    float mu  = s * invD;
    float var = s2 * invD - mu * mu;
    float inv = rsqrtf(var + EPS_LN);
    float* yr = y + (size_t)row * DD;
    bool is_last = ((row & (TT - 1)) == (TT - 1));
    float* lr = last_out + (size_t)(row >> 10) * DD;
    #pragma unroll
    for (int i = threadIdx.x; i < DD; i += 256) {
        float v = (xr[i] - mu) * inv * gamma[i] + beta[i];
        yr[i] = v;
        if (is_last) lr[i] = v;
    }
}

// ---------------- token-shift mix -> fp16 ----------------
__global__ __launch_bounds__(256)
void mix_h(const float* __restrict__ xn, const float* __restrict__ init,
           const float* __restrict__ mk, const float* __restrict__ mv,
           const float* __restrict__ mr,
           __half* __restrict__ ok, __half* __restrict__ ov,
           __half* __restrict__ orr) {
    size_t idx = (size_t)blockIdx.x * 256 + threadIdx.x;
    int d = (int)(idx & (DD - 1));
    size_t row = idx >> 10;
    int t = (int)(row & (TT - 1));
    int b = (int)(row >> 10);
    float cur  = xn[idx];
    float prev = t ? xn[idx - DD] : init[(size_t)b * DD + d];
    float m;
    m = mk[d]; ok[idx]  = __float2half(m * cur + (1.f - m) * prev);
    if (ov) { m = mv[d]; ov[idx] = __float2half(m * cur + (1.f - m) * prev); }
    m = mr[d]; orr[idx] = __float2half(m * cur + (1.f - m) * prev);
}

// ---------------- r * wkv -> fp16 ----------------
__global__ __launch_bounds__(256)
void mul_h(const float* __restrict__ a, const float* __restrict__ b,
           __half* __restrict__ o) {
    size_t idx = (size_t)blockIdx.x * 256 + threadIdx.x;
    o[idx] = __float2half(a[idx] * b[idx]);
}

// ---------------- weight split + transpose: W[K,N] fp32 -> WT hi/lo [N,K] fp16 ----------------
__global__ __launch_bounds__(256)
void wsplit_t(const float* __restrict__ W, __half* __restrict__ hi,
              __half* __restrict__ lo, int Kdim, int Ndim) {
    __shared__ float t[32][33];
    int n0 = blockIdx.x * 32, k0 = blockIdx.y * 32;
    int tx = threadIdx.x, ty = threadIdx.y;
    #pragma unroll
    for (int i = ty; i < 32; i += 8)
        t[i][tx] = W[(size_t)(k0 + i) * Ndim + n0 + tx];
    __syncthreads();
    #pragma unroll
    for (int i = ty; i < 32; i += 8) {
        float v = t[tx][i];
        size_t o = (size_t)(n0 + i) * Kdim + k0 + tx;
        __half h = __float2half(v);
        hi[o] = h;
        lo[o] = __float2half(v - __half2float(h));
    }
}

// ---------------- WKV scan ----------------
__global__ __launch_bounds__(64)
void wkv_scan(const float* __restrict__ kbuf, const float* __restrict__ vbuf,
              const float* __restrict__ a0, const float* __restrict__ b0,
              const float* __restrict__ p0,
              const float* __restrict__ decay, const float* __restrict__ first,
              float* __restrict__ wkvbuf,
              float* __restrict__ aa_out, float* __restrict__ bb_out,
              float* __restrict__ pp_out) {
    int idx = blockIdx.x * 64 + threadIdx.x;   // 0 .. B*D-1
    int d = idx & (DD - 1);
    int b = idx >> 10;
    float w = -__expf(decay[d]);
    float u = first[d];
    float aa = a0[idx], bb = b0[idx], pp = p0[idx];
    const float* kp = kbuf + (size_t)b * TT * DD + d;
    const float* vp = vbuf + (size_t)b * TT * DD + d;
    float* op = wkvbuf + (size_t)b * TT * DD + d;
    #pragma unroll 4
    for (int t = 0; t < TT; t++) {
        float kt = kp[(size_t)t * DD];
        float vt = vp[(size_t)t * DD];
        float ww = u + kt;
        float p  = fmaxf(pp, ww);
        float e1 = __expf(pp - p);
        float e2 = __expf(ww - p);
        op[(size_t)t * DD] = (e1 * aa + e2 * vt) / (e1 * bb + e2);
        float ww2 = pp + w;
        float p2  = fmaxf(ww2, kt);
        float e1b = __expf(ww2 - p2);
        float e2b = __expf(kt - p2);
        aa = e1b * aa + e2b * vt;
        bb = e1b * bb + e2b;
        pp = p2;
    }
    aa_out[idx] = aa; bb_out[idx] = bb; pp_out[idx] = pp;
}

// ---------------- fp16 x2 mma.sync GEMM: C[M,N] = A[M,K] @ (Wh+Wl)^T (W stored [N,K]) ----------------
// CTA tile 256x128, BK=32, 512 threads / 16 warps (warp tile 64x32), 4-stage cp.async.
#define ROWP 80                         // smem row pitch bytes (32 fp16 + 8 pad)
#define OFF_B1 20480                    // A = 256*80
#define OFF_B2 30720                    // + 128*80
#define STAGEB 40960                    // A + Bh + Bl
#define NSTAGE 4
#define GEMM_SMEM (NSTAGE * STAGEB)     // 163840

__device__ __forceinline__ void epi_pair(float v0, float v1, size_t base,
                                         int act,
                                         const float* __restrict__ mulp,
                                         const float* __restrict__ addp,
                                         float* __restrict__ Cf,
                                         __half* __restrict__ Ch) {
    if (act == 1) {
        v0 = 1.f / (1.f + __expf(-v0));
        v1 = 1.f / (1.f + __expf(-v1));
    } else if (act == 2) {
        v0 = fmaxf(v0, 0.f); v0 *= v0;
        v1 = fmaxf(v1, 0.f); v1 *= v1;
    }
    if (mulp) { float2 m = *(const float2*)(mulp + base); v0 *= m.x; v1 *= m.y; }
    if (addp) { float2 a = *(const float2*)(addp + base); v0 += a.x; v1 += a.y; }
    if (Cf) { float2 o; o.x = v0; o.y = v1; *(float2*)(Cf + base) = o; }
    if (Ch) {
        __half2 h = __floats2half2_rn(v0, v1);
        *(__half2*)(Ch + base) = h;
    }
}

__global__ __launch_bounds__(512, 1)
void mma_gemm(const __half* __restrict__ A,
              const __half* __restrict__ Bhi, const __half* __restrict__ Blo,
              int Kn, int Nn,
              float* __restrict__ Cf, __half* __restrict__ Ch,
              int act, const float* __restrict__ mulp, const float* __restrict__ addp) {
    extern __shared__ char sm[];
    const uint32_t sbase = smem_u32(sm);
    const int tid = threadIdx.x;
    const int lane = tid & 31, wid = tid >> 5;
    const int m0 = blockIdx.y * 256, n0 = blockIdx.x * 128;
    const int KT = Kn >> 5;
    const int wm = (wid >> 2) * 64;   // warp m offset (0..192)
    const int wn = (wid & 3) * 32;    // warp n offset (0..96)

    float acc[4][4][4];
    #pragma unroll
    for (int t = 0; t < 4; t++)
        #pragma unroll
        for (int j = 0; j < 4; j++)
            #pragma unroll
            for (int q = 0; q < 4; q++) acc[t][j][q] = 0.f;

    auto issue = [&](int kt) {
        const int slot = kt % NSTAGE;
        const uint32_t st = sbase + slot * STAGEB;
        const size_t k0 = (size_t)kt << 5;
        // A: 256 rows x 4 chunks of 16B = 1024 chunks
        #pragma unroll
        for (int h = 0; h < 2; h++) {
            int idx = tid + h * 512;
            int row = idx >> 2, ch = idx & 3;
            cpa16(st + (uint32_t)row * ROWP + ch * 16,
                  A + (size_t)(m0 + row) * Kn + k0 + ch * 8);
        }
        // B hi/lo: 128 rows x 4 chunks each
        {
            int row = tid >> 2, ch = tid & 3;
            uint32_t doff = (uint32_t)row * ROWP + ch * 16;
            size_t boff = (size_t)(n0 + row) * Kn + k0 + ch * 8;
            cpa16(st + OFF_B1 + doff, Bhi + boff);
            cpa16(st + OFF_B2 + doff, Blo + boff);
        }
        CP_COMMIT();
    };

    issue(0);
    issue(1);
    issue(2);

    for (int kt = 0; kt < KT; kt++) {
        CP_WAIT(2);
        __syncthreads();
        const uint32_t st = sbase + (kt % NSTAGE) * STAGEB;
        #pragma unroll
        for (int ks = 0; ks < 2; ks++) {
            const int k0 = ks * 16;
            uint32_t ah[4][4], bh[4][2], bl[4][2];
            #pragma unroll
            for (int t = 0; t < 4; t++) {
                uint32_t ad = st + (uint32_t)(wm + t * 16 + (lane & 15)) * ROWP
                            + (k0 + (lane >> 4) * 8) * 2;
                ldsm4(ah[t], ad);
            }
            {
                int g = lane >> 3, r = lane & 7;
                int n = wn + (g >> 1) * 8 + r;
                int k = k0 + (g & 1) * 8;
                uint32_t bd = st + OFF_B1 + (uint32_t)n * ROWP + k * 2;
                ldsm4(&bh[0][0], bd);
                ldsm4(&bh[2][0], bd + 16 * ROWP);
                bd += OFF_B2 - OFF_B1;
                ldsm4(&bl[0][0], bd);
                ldsm4(&bl[2][0], bd + 16 * ROWP);
            }
            #pragma unroll
            for (int t = 0; t < 4; t++)
                #pragma unroll
                for (int j = 0; j < 4; j++)
                    mma_fp16(acc[t][j], ah[t], bh[j]);
            #pragma unroll
            for (int t = 0; t < 4; t++)
                #pragma unroll
                for (int j = 0; j < 4; j++)
                    mma_fp16(acc[t][j], ah[t], bl[j]);
        }
        if (kt + 3 < KT) issue(kt + 3);
    }
    CP_WAIT(0);

    // ---- epilogue ----
    #pragma unroll
    for (int t = 0; t < 4; t++) {
        int row = m0 + wm + t * 16 + (lane >> 2);
        #pragma unroll
        for (int j = 0; j < 4; j++) {
            int col = n0 + wn + j * 8 + ((lane & 3) << 1);
            size_t b0 = (size_t)row * Nn + col;
            size_t b1 = (size_t)(row + 8) * Nn + col;
            epi_pair(acc[t][j][0], acc[t][j][1], b0, act, mulp, addp, Cf, Ch);
            epi_pair(acc[t][j][2], acc[t][j][3], b1, act, mulp, addp, Cf, Ch);
        }
    }
}

// ---------------- host driver ----------------
extern "C" void kernel_launch(void* const* d_in, const int* in_sizes, int n_in,
                              void* d_out, int out_size) {
    const float* x        = (const float*)d_in[0];
    const float* att_x    = (const float*)d_in[1];
    const float* att_a    = (const float*)d_in[2];
    const float* att_b    = (const float*)d_in[3];
    const float* att_p    = (const float*)d_in[4];
    const float* ffn_x    = (const float*)d_in[5];
    const float* ln1_g    = (const float*)d_in[6];
    const float* ln1_b    = (const float*)d_in[7];
    const float* ln2_g    = (const float*)d_in[8];
    const float* ln2_b    = (const float*)d_in[9];
    const float* tm_mix_k = (const float*)d_in[10];
    const float* tm_mix_v = (const float*)d_in[11];
    const float* tm_mix_r = (const float*)d_in[12];
    const float* tm_decay = (const float*)d_in[13];
    const float* tm_first = (const float*)d_in[14];
    const float* Wk       = (const float*)d_in[15];
    const float* Wv       = (const float*)d_in[16];
    const float* Wr       = (const float*)d_in[17];
    const float* Wo       = (const float*)d_in[18];
    const float* cm_mix_k = (const float*)d_in[19];
    const float* cm_mix_r = (const float*)d_in[20];
    const float* Ck       = (const float*)d_in[21];
    const float* Cr       = (const float*)d_in[22];
    const float* Cv       = (const float*)d_in[23];

    float* out      = (float*)d_out;
    float* xn_last  = out + (size_t)MM * DD;
    float* aa_out   = xn_last  + (size_t)BB * DD;
    float* bb_out   = aa_out   + (size_t)BB * DD;
    float* pp_out   = bb_out   + (size_t)BB * DD;
    float* xn2_last = pp_out   + (size_t)BB * DD;

    float *xn, *kb, *vb, *rb, *wkv, *x1, *xn2, *rc;
    __half *ak, *av, *ar, *kc;
    __half *wkh, *wkl, *wvh, *wvl, *wrh, *wrl, *woh, *wol;
    __half *crh, *crl, *ckh, *ckl, *cvh, *cvl;
    cudaGetSymbolAddress((void**)&xn,  g_xn);
    cudaGetSymbolAddress((void**)&kb,  g_kb);
    cudaGetSymbolAddress((void**)&vb,  g_vb);
    cudaGetSymbolAddress((void**)&rb,  g_rb);
    cudaGetSymbolAddress((void**)&wkv, g_wkv);
    cudaGetSymbolAddress((void**)&x1,  g_x1);
    cudaGetSymbolAddress((void**)&xn2, g_xn2);
    cudaGetSymbolAddress((void**)&rc,  g_rc);
    cudaGetSymbolAddress((void**)&ak,  g_ak);
    cudaGetSymbolAddress((void**)&av,  g_av);
    cudaGetSymbolAddress((void**)&ar,  g_ar);
    cudaGetSymbolAddress((void**)&kc,  g_kc);
    cudaGetSymbolAddress((void**)&wkh, g_wkh); cudaGetSymbolAddress((void**)&wkl, g_wkl);
    cudaGetSymbolAddress((void**)&wvh, g_wvh); cudaGetSymbolAddress((void**)&wvl, g_wvl);
    cudaGetSymbolAddress((void**)&wrh, g_wrh); cudaGetSymbolAddress((void**)&wrl, g_wrl);
    cudaGetSymbolAddress((void**)&woh, g_woh); cudaGetSymbolAddress((void**)&wol, g_wol);
    cudaGetSymbolAddress((void**)&crh, g_crh); cudaGetSymbolAddress((void**)&crl, g_crl);
    cudaGetSymbolAddress((void**)&ckh, g_ckh); cudaGetSymbolAddress((void**)&ckl, g_ckl);
    cudaGetSymbolAddress((void**)&cvh, g_cvh); cudaGetSymbolAddress((void**)&cvl, g_cvl);

    cudaFuncSetAttribute(mma_gemm, cudaFuncAttributeMaxDynamicSharedMemorySize, GEMM_SMEM);

    const int ELT_BLOCKS = (int)(((size_t)MM * DD) / 256);  // 32768
    dim3 wt_thr(32, 8);
    dim3 g1k(DD / 128, MM / 256);   // (8, 32)
    dim3 g4k(FF / 128, MM / 256);   // (32, 32)

    // ---- time mixing ----
    wsplit_t<<<dim3(DD/32, DD/32), wt_thr>>>(Wk, wkh, wkl, DD, DD);           // 0
    wsplit_t<<<dim3(DD/32, DD/32), wt_thr>>>(Wv, wvh, wvl, DD, DD);           // 1
    wsplit_t<<<dim3(DD/32, DD/32), wt_thr>>>(Wr, wrh, wrl, DD, DD);           // 2
    ln_kernel<<<MM, 256>>>(x, ln1_g, ln1_b, xn, xn_last);                     // 3
    mix_h<<<ELT_BLOCKS, 256>>>(xn, att_x, tm_mix_k, tm_mix_v, tm_mix_r,
                               ak, av, ar);                                   // 4
    mma_gemm<<<g1k, 512, GEMM_SMEM>>>(ak, wkh, wkl, DD, DD,
                                      kb, nullptr, 0, nullptr, nullptr);      // 5 <- profiled
    mma_gemm<<<g1k, 512, GEMM_SMEM>>>(av, wvh, wvl, DD, DD,
                                      vb, nullptr, 0, nullptr, nullptr);
    mma_gemm<<<g1k, 512, GEMM_SMEM>>>(ar, wrh, wrl, DD, DD,
                                      rb, nullptr, 1, nullptr, nullptr);

    wkv_scan<<<(BB * DD) / 64, 64>>>(kb, vb, att_a, att_b, att_p,
                                     tm_decay, tm_first, wkv,
                                     aa_out, bb_out, pp_out);

    wsplit_t<<<dim3(DD/32, DD/32), wt_thr>>>(Wo, woh, wol, DD, DD);
    mul_h<<<ELT_BLOCKS, 256>>>(rb, wkv, av);            // av := fp16(r * wkv)
    mma_gemm<<<g1k, 512, GEMM_SMEM>>>(av, woh, wol, DD, DD,
                                      x1, nullptr, 0, nullptr, x);

    // ---- channel mixing ----
    wsplit_t<<<dim3(DD/32, DD/32), wt_thr>>>(Cr, crh, crl, DD, DD);
    wsplit_t<<<dim3(FF/32, DD/32), wt_thr>>>(Ck, ckh, ckl, DD, FF);  // -> [FF,DD]
    wsplit_t<<<dim3(DD/32, FF/32), wt_thr>>>(Cv, cvh, cvl, FF, DD);  // -> [DD,FF]
    ln_kernel<<<MM, 256>>>(x1, ln2_g, ln2_b, xn2, xn2_last);
    mix_h<<<ELT_BLOCKS, 256>>>(xn2, ffn_x, cm_mix_k, nullptr, cm_mix_r,
                               ak, nullptr, ar);
    mma_gemm<<<g4k, 512, GEMM_SMEM>>>(ak, ckh, ckl, DD, FF,
                                      nullptr, kc, 2, nullptr, nullptr);  // relu^2 -> fp16
    mma_gemm<<<g1k, 512, GEMM_SMEM>>>(ar, crh, crl, DD, DD,
                                      rc, nullptr, 1, nullptr, nullptr);
    mma_gemm<<<g1k, 512, GEMM_SMEM>>>(kc, cvh, cvl, FF, DD,
                                      out, nullptr, 0, rc, x1);
}

// round 10
// speedup vs baseline: 4.4494x; 1.2589x over previous
#include <cuda_runtime.h>
#include <cuda_fp16.h>
#include <cuda_bf16.h>
#include <cstdint>

// ---------------- problem constants ----------------
#define BB 8
#define TT 1024
#define DD 1024
#define FF 4096
#define MM (BB * TT)          // 8192 rows
#define EPS_LN 1e-3f

// ---------------- PTX helpers ----------------
__device__ __forceinline__ uint32_t smem_u32(const void* p) {
    uint32_t a;
    asm("{ .reg .u64 t; cvta.to.shared.u64 t, %1; cvt.u32.u64 %0, t; }"
        : "=r"(a) : "l"(p));
    return a;
}

__device__ __forceinline__ void cpa16(uint32_t dst, const void* src) {
    asm volatile("cp.async.cg.shared.global [%0], [%1], 16;"
                 :: "r"(dst), "l"(src) : "memory");
}
#define CP_COMMIT() asm volatile("cp.async.commit_group;" ::: "memory")
#define CP_WAIT(n)  asm volatile("cp.async.wait_group %0;" :: "n"(n) : "memory")

__device__ __forceinline__ void ldsm4(uint32_t* r, uint32_t a) {
    asm volatile("ldmatrix.sync.aligned.m8n8.x4.shared.b16 {%0,%1,%2,%3}, [%4];"
                 : "=r"(r[0]), "=r"(r[1]), "=r"(r[2]), "=r"(r[3]) : "r"(a));
}

__device__ __forceinline__ void mma_fp16(float* c, const uint32_t* a, const uint32_t* b) {
    asm volatile(
        "mma.sync.aligned.m16n8k16.row.col.f32.f16.f16.f32 "
        "{%0,%1,%2,%3}, {%4,%5,%6,%7}, {%8,%9}, {%0,%1,%2,%3};"
        : "+f"(c[0]), "+f"(c[1]), "+f"(c[2]), "+f"(c[3])
        : "r"(a[0]), "r"(a[1]), "r"(a[2]), "r"(a[3]), "r"(b[0]), "r"(b[1]));
}

// ---------------- scratch (static device globals) ----------------
__device__ float g_xn [(size_t)MM * DD];
__device__ float g_kb [(size_t)MM * DD];
__device__ float g_vb [(size_t)MM * DD];
__device__ float g_rb [(size_t)MM * DD];
__device__ float g_wkv[(size_t)MM * DD];
__device__ float g_x1 [(size_t)MM * DD];
__device__ float g_xn2[(size_t)MM * DD];
__device__ float g_rc [(size_t)MM * DD];
// fp16 activations
__device__ __half g_ak[(size_t)MM * DD];
__device__ __half g_av[(size_t)MM * DD];
__device__ __half g_ar[(size_t)MM * DD];
__device__ __half g_kc[(size_t)MM * FF];
// fp16 transposed weights [N, K]
__device__ __half g_wk[(size_t)DD * DD];
__device__ __half g_wv[(size_t)DD * DD];
__device__ __half g_wr[(size_t)DD * DD];
__device__ __half g_wo[(size_t)DD * DD];
__device__ __half g_cr[(size_t)DD * DD];
__device__ __half g_ck[(size_t)FF * DD];   // Ck^T
__device__ __half g_cv[(size_t)DD * FF];   // Cv^T

// ---------------- LayerNorm ----------------
__global__ __launch_bounds__(256)
void ln_kernel(const float* __restrict__ x, const float* __restrict__ gamma,
               const float* __restrict__ beta, float* __restrict__ y,
               float* __restrict__ last_out) {
    __shared__ float red0[8], red1[8];
    int row = blockIdx.x;
    const float* xr = x + (size_t)row * DD;
    float s = 0.f, s2 = 0.f;
    #pragma unroll
    for (int i = threadIdx.x; i < DD; i += 256) {
        float v = xr[i];
        s += v; s2 += v * v;
    }
    #pragma unroll
    for (int o = 16; o; o >>= 1) {
        s  += __shfl_down_sync(0xffffffffu, s,  o);
        s2 += __shfl_down_sync(0xffffffffu, s2, o);
    }
    int lane = threadIdx.x & 31, wid = threadIdx.x >> 5;
    if (lane == 0) { red0[wid] = s; red1[wid] = s2; }
    __syncthreads();
    s = 0.f; s2 = 0.f;
    #pragma unroll
    for (int i = 0; i < 8; i++) { s += red0[i]; s2 += red1[i]; }
    const float invD = 1.0f / DD;
    float mu  = s * invD;
    float var = s2 * invD - mu * mu;
    float inv = rsqrtf(var + EPS_LN);
    float* yr = y + (size_t)row * DD;
    bool is_last = ((row & (TT - 1)) == (TT - 1));
    float* lr = last_out + (size_t)(row >> 10) * DD;
    #pragma unroll
    for (int i = threadIdx.x; i < DD; i += 256) {
        float v = (xr[i] - mu) * inv * gamma[i] + beta[i];
        yr[i] = v;
        if (is_last) lr[i] = v;
    }
}

// ---------------- token-shift mix -> fp16 ----------------
__global__ __launch_bounds__(256)
void mix_h(const float* __restrict__ xn, const float* __restrict__ init,
           const float* __restrict__ mk, const float* __restrict__ mv,
           const float* __restrict__ mr,
           __half* __restrict__ ok, __half* __restrict__ ov,
           __half* __restrict__ orr) {
    size_t idx = (size_t)blockIdx.x * 256 + threadIdx.x;
    int d = (int)(idx & (DD - 1));
    size_t row = idx >> 10;
    int t = (int)(row & (TT - 1));
    int b = (int)(row >> 10);
    float cur  = xn[idx];
    float prev = t ? xn[idx - DD] : init[(size_t)b * DD + d];
    float m;
    m = mk[d]; ok[idx]  = __float2half(m * cur + (1.f - m) * prev);
    if (ov) { m = mv[d]; ov[idx] = __float2half(m * cur + (1.f - m) * prev); }
    m = mr[d]; orr[idx] = __float2half(m * cur + (1.f - m) * prev);
}

// ---------------- r * wkv -> fp16 ----------------
__global__ __launch_bounds__(256)
void mul_h(const float* __restrict__ a, const float* __restrict__ b,
           __half* __restrict__ o) {
    size_t idx = (size_t)blockIdx.x * 256 + threadIdx.x;
    o[idx] = __float2half(a[idx] * b[idx]);
}

// ---------------- weight convert + transpose: W[K,N] fp32 -> WT [N,K] fp16 ----------------
__global__ __launch_bounds__(256)
void wconv_t(const float* __restrict__ W, __half* __restrict__ o,
             int Kdim, int Ndim) {
    __shared__ float t[32][33];
    int n0 = blockIdx.x * 32, k0 = blockIdx.y * 32;
    int tx = threadIdx.x, ty = threadIdx.y;
    #pragma unroll
    for (int i = ty; i < 32; i += 8)
        t[i][tx] = W[(size_t)(k0 + i) * Ndim + n0 + tx];
    __syncthreads();
    #pragma unroll
    for (int i = ty; i < 32; i += 8)
        o[(size_t)(n0 + i) * Kdim + k0 + tx] = __float2half(t[tx][i]);
}

// ---------------- WKV scan ----------------
__global__ __launch_bounds__(64)
void wkv_scan(const float* __restrict__ kbuf, const float* __restrict__ vbuf,
              const float* __restrict__ a0, const float* __restrict__ b0,
              const float* __restrict__ p0,
              const float* __restrict__ decay, const float* __restrict__ first,
              float* __restrict__ wkvbuf,
              float* __restrict__ aa_out, float* __restrict__ bb_out,
              float* __restrict__ pp_out) {
    int idx = blockIdx.x * 64 + threadIdx.x;   // 0 .. B*D-1
    int d = idx & (DD - 1);
    int b = idx >> 10;
    float w = -__expf(decay[d]);
    float u = first[d];
    float aa = a0[idx], bb = b0[idx], pp = p0[idx];
    const float* kp = kbuf + (size_t)b * TT * DD + d;
    const float* vp = vbuf + (size_t)b * TT * DD + d;
    float* op = wkvbuf + (size_t)b * TT * DD + d;
    #pragma unroll 4
    for (int t = 0; t < TT; t++) {
        float kt = kp[(size_t)t * DD];
        float vt = vp[(size_t)t * DD];
        float ww = u + kt;
        float p  = fmaxf(pp, ww);
        float e1 = __expf(pp - p);
        float e2 = __expf(ww - p);
        op[(size_t)t * DD] = (e1 * aa + e2 * vt) / (e1 * bb + e2);
        float ww2 = pp + w;
        float p2  = fmaxf(ww2, kt);
        float e1b = __expf(ww2 - p2);
        float e2b = __expf(kt - p2);
        aa = e1b * aa + e2b * vt;
        bb = e1b * bb + e2b;
        pp = p2;
    }
    aa_out[idx] = aa; bb_out[idx] = bb; pp_out[idx] = pp;
}

// ---------------- fp16 mma.sync GEMM: C[M,N] = A[M,K] @ W^T (W stored [N,K]) ----------------
// CTA tile 256x128, BK=32, 512 threads / 16 warps (warp tile 64x32), 5-stage cp.async.
#define ROWP 80                         // smem row pitch bytes (32 fp16 + 8 pad)
#define OFF_B 20480                     // A = 256*80
#define STAGEB 30720                    // A + B
#define NSTAGE 5
#define GEMM_SMEM (NSTAGE * STAGEB)     // 153600

__device__ __forceinline__ void epi_pair(float v0, float v1, size_t base,
                                         int act,
                                         const float* __restrict__ mulp,
                                         const float* __restrict__ addp,
                                         float* __restrict__ Cf,
                                         __half* __restrict__ Ch) {
    if (act == 1) {
        v0 = 1.f / (1.f + __expf(-v0));
        v1 = 1.f / (1.f + __expf(-v1));
    } else if (act == 2) {
        v0 = fmaxf(v0, 0.f); v0 *= v0;
        v1 = fmaxf(v1, 0.f); v1 *= v1;
    }
    if (mulp) { float2 m = *(const float2*)(mulp + base); v0 *= m.x; v1 *= m.y; }
    if (addp) { float2 a = *(const float2*)(addp + base); v0 += a.x; v1 += a.y; }
    if (Cf) { float2 o; o.x = v0; o.y = v1; *(float2*)(Cf + base) = o; }
    if (Ch) {
        __half2 h = __floats2half2_rn(v0, v1);
        *(__half2*)(Ch + base) = h;
    }
}

__global__ __launch_bounds__(512, 1)
void mma_gemm(const __half* __restrict__ A, const __half* __restrict__ Bw,
              int Kn, int Nn,
              float* __restrict__ Cf, __half* __restrict__ Ch,
              int act, const float* __restrict__ mulp, const float* __restrict__ addp) {
    extern __shared__ char sm[];
    const uint32_t sbase = smem_u32(sm);
    const int tid = threadIdx.x;
    const int lane = tid & 31, wid = tid >> 5;
    const int m0 = blockIdx.y * 256, n0 = blockIdx.x * 128;
    const int KT = Kn >> 5;
    const int wm = (wid >> 2) * 64;   // warp m offset (0..192)
    const int wn = (wid & 3) * 32;    // warp n offset (0..96)

    float acc[4][4][4];
    #pragma unroll
    for (int t = 0; t < 4; t++)
        #pragma unroll
        for (int j = 0; j < 4; j++)
            #pragma unroll
            for (int q = 0; q < 4; q++) acc[t][j][q] = 0.f;

    auto issue = [&](int kt) {
        const int slot = kt % NSTAGE;
        const uint32_t st = sbase + slot * STAGEB;
        const size_t k0 = (size_t)kt << 5;
        // A: 256 rows x 4 chunks of 16B = 1024 chunks
        #pragma unroll
        for (int h = 0; h < 2; h++) {
            int idx = tid + h * 512;
            int row = idx >> 2, ch = idx & 3;
            cpa16(st + (uint32_t)row * ROWP + ch * 16,
                  A + (size_t)(m0 + row) * Kn + k0 + ch * 8);
        }
        // B: 128 rows x 4 chunks
        {
            int row = tid >> 2, ch = tid & 3;
            cpa16(st + OFF_B + (uint32_t)row * ROWP + ch * 16,
                  Bw + (size_t)(n0 + row) * Kn + k0 + ch * 8);
        }
        CP_COMMIT();
    };

    issue(0);
    issue(1);
    issue(2);
    issue(3);

    for (int kt = 0; kt < KT; kt++) {
        CP_WAIT(3);
        __syncthreads();
        const uint32_t st = sbase + (kt % NSTAGE) * STAGEB;
        #pragma unroll
        for (int ks = 0; ks < 2; ks++) {
            const int k0 = ks * 16;
            uint32_t ah[4][4], bh[4][2];
            #pragma unroll
            for (int t = 0; t < 4; t++) {
                uint32_t ad = st + (uint32_t)(wm + t * 16 + (lane & 15)) * ROWP
                            + (k0 + (lane >> 4) * 8) * 2;
                ldsm4(ah[t], ad);
            }
            {
                int g = lane >> 3, r = lane & 7;
                int n = wn + (g >> 1) * 8 + r;
                int k = k0 + (g & 1) * 8;
                uint32_t bd = st + OFF_B + (uint32_t)n * ROWP + k * 2;
                ldsm4(&bh[0][0], bd);
                ldsm4(&bh[2][0], bd + 16 * ROWP);
            }
            #pragma unroll
            for (int t = 0; t < 4; t++)
                #pragma unroll
                for (int j = 0; j < 4; j++)
                    mma_fp16(acc[t][j], ah[t], bh[j]);
        }
        if (kt + 4 < KT) issue(kt + 4);
    }
    CP_WAIT(0);

    // ---- epilogue ----
    #pragma unroll
    for (int t = 0; t < 4; t++) {
        int row = m0 + wm + t * 16 + (lane >> 2);
        #pragma unroll
        for (int j = 0; j < 4; j++) {
            int col = n0 + wn + j * 8 + ((lane & 3) << 1);
            size_t b0 = (size_t)row * Nn + col;
            size_t b1 = (size_t)(row + 8) * Nn + col;
            epi_pair(acc[t][j][0], acc[t][j][1], b0, act, mulp, addp, Cf, Ch);
            epi_pair(acc[t][j][2], acc[t][j][3], b1, act, mulp, addp, Cf, Ch);
        }
    }
}

// ---------------- host driver ----------------
extern "C" void kernel_launch(void* const* d_in, const int* in_sizes, int n_in,
                              void* d_out, int out_size) {
    const float* x        = (const float*)d_in[0];
    const float* att_x    = (const float*)d_in[1];
    const float* att_a    = (const float*)d_in[2];
    const float* att_b    = (const float*)d_in[3];
    const float* att_p    = (const float*)d_in[4];
    const float* ffn_x    = (const float*)d_in[5];
    const float* ln1_g    = (const float*)d_in[6];
    const float* ln1_b    = (const float*)d_in[7];
    const float* ln2_g    = (const float*)d_in[8];
    const float* ln2_b    = (const float*)d_in[9];
    const float* tm_mix_k = (const float*)d_in[10];
    const float* tm_mix_v = (const float*)d_in[11];
    const float* tm_mix_r = (const float*)d_in[12];
    const float* tm_decay = (const float*)d_in[13];
    const float* tm_first = (const float*)d_in[14];
    const float* Wk       = (const float*)d_in[15];
    const float* Wv       = (const float*)d_in[16];
    const float* Wr       = (const float*)d_in[17];
    const float* Wo       = (const float*)d_in[18];
    const float* cm_mix_k = (const float*)d_in[19];
    const float* cm_mix_r = (const float*)d_in[20];
    const float* Ck       = (const float*)d_in[21];
    const float* Cr       = (const float*)d_in[22];
    const float* Cv       = (const float*)d_in[23];

    float* out      = (float*)d_out;
    float* xn_last  = out + (size_t)MM * DD;
    float* aa_out   = xn_last  + (size_t)BB * DD;
    float* bb_out   = aa_out   + (size_t)BB * DD;
    float* pp_out   = bb_out   + (size_t)BB * DD;
    float* xn2_last = pp_out   + (size_t)BB * DD;

    float *xn, *kb, *vb, *rb, *wkv, *x1, *xn2, *rc;
    __half *ak, *av, *ar, *kc;
    __half *wk, *wv, *wr, *wo, *cr, *ck, *cv;
    cudaGetSymbolAddress((void**)&xn,  g_xn);
    cudaGetSymbolAddress((void**)&kb,  g_kb);
    cudaGetSymbolAddress((void**)&vb,  g_vb);
    cudaGetSymbolAddress((void**)&rb,  g_rb);
    cudaGetSymbolAddress((void**)&wkv, g_wkv);
    cudaGetSymbolAddress((void**)&x1,  g_x1);
    cudaGetSymbolAddress((void**)&xn2, g_xn2);
    cudaGetSymbolAddress((void**)&rc,  g_rc);
    cudaGetSymbolAddress((void**)&ak,  g_ak);
    cudaGetSymbolAddress((void**)&av,  g_av);
    cudaGetSymbolAddress((void**)&ar,  g_ar);
    cudaGetSymbolAddress((void**)&kc,  g_kc);
    cudaGetSymbolAddress((void**)&wk,  g_wk);
    cudaGetSymbolAddress((void**)&wv,  g_wv);
    cudaGetSymbolAddress((void**)&wr,  g_wr);
    cudaGetSymbolAddress((void**)&wo,  g_wo);
    cudaGetSymbolAddress((void**)&cr,  g_cr);
    cudaGetSymbolAddress((void**)&ck,  g_ck);
    cudaGetSymbolAddress((void**)&cv,  g_cv);

    cudaFuncSetAttribute(mma_gemm, cudaFuncAttributeMaxDynamicSharedMemorySize, GEMM_SMEM);

    const int ELT_BLOCKS = (int)(((size_t)MM * DD) / 256);  // 32768
    dim3 wt_thr(32, 8);
    dim3 g1k(DD / 128, MM / 256);   // (8, 32)
    dim3 g4k(FF / 128, MM / 256);   // (32, 32)

    // ---- time mixing ----
    wconv_t<<<dim3(DD/32, DD/32), wt_thr>>>(Wk, wk, DD, DD);                  // 0
    wconv_t<<<dim3(DD/32, DD/32), wt_thr>>>(Wv, wv, DD, DD);                  // 1
    wconv_t<<<dim3(DD/32, DD/32), wt_thr>>>(Wr, wr, DD, DD);                  // 2
    ln_kernel<<<MM, 256>>>(x, ln1_g, ln1_b, xn, xn_last);                     // 3
    mix_h<<<ELT_BLOCKS, 256>>>(xn, att_x, tm_mix_k, tm_mix_v, tm_mix_r,
                               ak, av, ar);                                   // 4
    mma_gemm<<<g1k, 512, GEMM_SMEM>>>(ak, wk, DD, DD,
                                      kb, nullptr, 0, nullptr, nullptr);      // 5 <- profiled
    mma_gemm<<<g1k, 512, GEMM_SMEM>>>(av, wv, DD, DD,
                                      vb, nullptr, 0, nullptr, nullptr);
    mma_gemm<<<g1k, 512, GEMM_SMEM>>>(ar, wr, DD, DD,
                                      rb, nullptr, 1, nullptr, nullptr);

    wkv_scan<<<(BB * DD) / 64, 64>>>(kb, vb, att_a, att_b, att_p,
                                     tm_decay, tm_first, wkv,
                                     aa_out, bb_out, pp_out);

    wconv_t<<<dim3(DD/32, DD/32), wt_thr>>>(Wo, wo, DD, DD);
    mul_h<<<ELT_BLOCKS, 256>>>(rb, wkv, av);            // av := fp16(r * wkv)
    mma_gemm<<<g1k, 512, GEMM_SMEM>>>(av, wo, DD, DD,
                                      x1, nullptr, 0, nullptr, x);

    // ---- channel mixing ----
    wconv_t<<<dim3(DD/32, DD/32), wt_thr>>>(Cr, cr, DD, DD);
    wconv_t<<<dim3(FF/32, DD/32), wt_thr>>>(Ck, ck, DD, FF);  // -> [FF,DD]
    wconv_t<<<dim3(DD/32, FF/32), wt_thr>>>(Cv, cv, FF, DD);  // -> [DD,FF]
    ln_kernel<<<MM, 256>>>(x1, ln2_g, ln2_b, xn2, xn2_last);
    mix_h<<<ELT_BLOCKS, 256>>>(xn2, ffn_x, cm_mix_k, nullptr, cm_mix_r,
                               ak, nullptr, ar);
    mma_gemm<<<g4k, 512, GEMM_SMEM>>>(ak, ck, DD, FF,
                                      nullptr, kc, 2, nullptr, nullptr);  // relu^2 -> fp16
    mma_gemm<<<g1k, 512, GEMM_SMEM>>>(ar, cr, DD, DD,
                                      rc, nullptr, 1, nullptr, nullptr);
    mma_gemm<<<g1k, 512, GEMM_SMEM>>>(kc, cv, FF, DD,
                                      out, nullptr, 0, rc, x1);
}